// round 12
// baseline (speedup 1.0000x reference)
#include <cuda_runtime.h>

#define HH 376
#define WW 376
#define HWX (HH*WW)          // 141376
#define NHM (3*HWX)          // 424128
#define KTOP 500
#define CANDS 4096

// ---------------- scratch (device globals: no allocation allowed) ----------------
__device__ float g_shared[64 * HWX];     // shared conv output (BN+ReLU)
__device__ float g_h[64 * HWX];          // hm branch conv1 output
__device__ float g_hm[3 * HWX];          // sigmoid heatmap
__device__ float g_Ush[16 * 256 * 64];   // winograd weights shared conv: [k16][ic][oc]
__device__ float g_U1[16 * 64 * 64];     // winograd weights hm conv1 (branch 0)
__device__ float g_W1t[6 * 64 * 64 * 9]; // [b][ic][oc][9] (for sparse path)
__device__ float g_sc_sh[64], g_bi_sh[64];
__device__ float g_sc1[6 * 64], g_bi1[6 * 64];
__device__ unsigned int g_hist1[2048], g_hist2[2048];
__device__ unsigned int g_T1, g_above1, g_T2;
__device__ unsigned int g_cand_count;
__device__ float g_cand_val[CANDS];
__device__ int   g_cand_idx[CANDS];
__device__ float g_topk_val[512];
__device__ int   g_topk_idx[512];
__device__ float g_gather[5 * KTOP * 3]; // [branch-1][det][3]

// ---------------- merged setup: zero hists/out + BN prep ----------------
__global__ void setup_k(const float* __restrict__ bn_sh, const float* __restrict__ bn1s,
                        float* __restrict__ out, int out_n) {
    int i = blockIdx.x * blockDim.x + threadIdx.x;
    if (i < 2048) { g_hist1[i] = 0u; g_hist2[i] = 0u; }
    if (i == 0) g_cand_count = 0u;
    if (i < out_n) out[i] = 0.f;
    if (i < 64) {
        int c = i;
        float g = bn_sh[0*64+c], b = bn_sh[1*64+c], m = bn_sh[2*64+c], v = bn_sh[3*64+c];
        float sc = g * rsqrtf(v + 1e-5f);
        g_sc_sh[c] = sc; g_bi_sh[c] = b - m * sc;
        for (int br = 0; br < 6; br++) {
            const float* p = bn1s + br * 4 * 64;
            float g1 = p[0*64+c], b1 = p[1*64+c], m1 = p[2*64+c], v1 = p[3*64+c];
            float s1 = g1 * rsqrtf(v1 + 1e-5f);
            g_sc1[br*64+c] = s1; g_bi1[br*64+c] = b1 - m1 * s1;
        }
    }
}

// ---------------- Winograd weight transform: U = G g G^T ----------------
// G = [[1,0,0],[.5,.5,.5],[.5,-.5,.5],[0,0,1]]
__device__ __forceinline__ void wg_fill(const float* __restrict__ g9, float u[4][4]) {
    float t[4][3];
    #pragma unroll
    for (int c = 0; c < 3; c++) {
        float g0 = g9[0*3+c], g1 = g9[1*3+c], g2 = g9[2*3+c];
        t[0][c] = g0;
        t[1][c] = 0.5f*(g0 + g1 + g2);
        t[2][c] = 0.5f*(g0 - g1 + g2);
        t[3][c] = g2;
    }
    #pragma unroll
    for (int r = 0; r < 4; r++) {
        float a = t[r][0], b = t[r][1], c = t[r][2];
        u[r][0] = a;
        u[r][1] = 0.5f*(a + b + c);
        u[r][2] = 0.5f*(a - b + c);
        u[r][3] = c;
    }
}

// W_sh [oc64][ic256][9] -> g_Ush [k16][ic][oc]
__global__ void wg_transform_sh_k(const float* __restrict__ w) {
    int i = blockIdx.x * blockDim.x + threadIdx.x;
    if (i >= 64*256) return;
    int ic = i % 256, oc = i / 256;
    float u[4][4];
    wg_fill(w + (size_t)i*9, u);
    #pragma unroll
    for (int r = 0; r < 4; r++)
        #pragma unroll
        for (int c = 0; c < 4; c++)
            g_Ush[(r*4+c)*(256*64) + ic*64 + oc] = u[r][c];
}

// W1s branch 0 [oc64][ic64][9] -> g_U1 [k16][ic][oc]
__global__ void wg_transform_w1_k(const float* __restrict__ w) {
    int i = blockIdx.x * blockDim.x + threadIdx.x;
    if (i >= 64*64) return;
    int ic = i % 64, oc = i / 64;
    float u[4][4];
    wg_fill(w + (size_t)i*9, u);
    #pragma unroll
    for (int r = 0; r < 4; r++)
        #pragma unroll
        for (int c = 0; c < 4; c++)
            g_U1[(r*4+c)*(64*64) + ic*64 + oc] = u[r][c];
}

// W1s [b][oc64][ic64][9] -> g_W1t [b][ic][oc][9]  (sparse path)
__global__ void transpose_w1_k(const float* __restrict__ w) {
    int i = blockIdx.x * blockDim.x + threadIdx.x;
    if (i >= 6*64*64*9) return;
    int k = i % 9; int r = i / 9; int ic = r % 64; r /= 64; int oc = r % 64; int b = r / 64;
    g_W1t[(((b*64 + ic)*64) + oc)*9 + k] = w[i];
}

// ---------------- Winograd F(2x2,3x3) conv + BN + ReLU (Cout=64) ----------------
// MODE 0: in = x (arg, CIN=256), U = g_Ush, out g_shared
// MODE 1: in = g_shared (CIN=64), U = g_U1, out g_h
// Block: 256 threads, 4x4 output tiles (8x8 px), 32 oc (gridDim.z=2 splits oc).
// IC_BATCH=4 per round; register-resident float2 U double-buffer; 3 CTAs/SM.
template<int CIN, int MODE>
__global__ __launch_bounds__(256, 3)
void winograd_k(const float* __restrict__ xin)
{
    const float* __restrict__ in = (MODE == 0) ? xin : g_shared;
    const float* __restrict__ Ug = (MODE == 0) ? g_Ush : g_U1;
    const float* __restrict__ sc = (MODE == 0) ? g_sc_sh : g_sc1;
    const float* __restrict__ bi = (MODE == 0) ? g_bi_sh : g_bi1;
    float* __restrict__ out      = (MODE == 0) ? g_shared : g_h;

    __shared__ union {
        struct {
            float V[4][16][16];   // [icb][k][tile] rows contiguous (LDS.128 in core)
            float d[4][112];      // [icb][r*11+c], 110 used
        } ph;
        float M[16][32][17];      // epilogue exchange: [k][oc_local][tile], padded
    } sm;

    const int tid = threadIdx.x;
    const int ox0 = blockIdx.x * 8, oy0 = blockIdx.y * 8;
    const int oc0 = blockIdx.z * 32;
    const int k = tid >> 4;      // transform point 0..15 (V + core)
    const int slot = tid & 15;   // V-phase tile / core oc-group (2 oc)

    // ---- d-load slots (2 strided: i = tid, tid+256 over 400 elements) ----
    int goff0 = 0, goff1 = 0, smoff0 = 0, smoff1 = 0;
    bool inb0 = false, inb1 = false;
    {
        int p = tid % 100, icb = tid / 100;
        int lr = p / 10, lc = p % 10;
        int gy = oy0 - 1 + lr, gx = ox0 - 1 + lc;
        inb0 = (gy >= 0 && gy < HH && gx >= 0 && gx < WW);
        goff0 = icb*HWX + gy*WW + gx;
        smoff0 = icb*112 + lr*11 + lc;
    }
    const bool has1 = (tid < 144);
    if (has1) {
        int i = tid + 256;
        int p = i % 100, icb = i / 100;
        int lr = p / 10, lc = p % 10;
        int gy = oy0 - 1 + lr, gx = ox0 - 1 + lc;
        inb1 = (gy >= 0 && gy < HH && gx >= 0 && gx < WW);
        goff1 = icb*HWX + gy*WW + gx;
        smoff1 = icb*112 + lr*11 + lc;
    }

    // ---- V-phase constants: value at (vk=k, vtile=slot) ----
    const int va = k >> 2, vb = k & 3;
    // B^T combos: row0: d0-d2 ; row1: d1+d2 ; row2: d2-d1 ; row3: d1-d3
    const int ia0 = (va == 0) ? 0 : ((va == 2) ? 2 : 1);
    const int ia1 = (va < 2) ? 2 : ((va == 2) ? 1 : 3);
    const float sa = (va == 1) ? 1.f : -1.f;
    const int ib0 = (vb == 0) ? 0 : ((vb == 2) ? 2 : 1);
    const int ib1 = (vb < 2) ? 2 : ((vb == 2) ? 1 : 3);
    const float sb = (vb == 1) ? 1.f : -1.f;
    const int r0 = (slot >> 2)*2 + ia0, r1 = (slot >> 2)*2 + ia1;
    const int c0 = (slot & 3)*2 + ib0,  c1 = (slot & 3)*2 + ib1;
    const int a00 = r0*11 + c0, a01 = r0*11 + c1;
    const int a10 = r1*11 + c0, a11 = r1*11 + c1;

    // ---- U pointer: float2 per (k, ic, slot) — this block's 32-oc half ----
    const float2* up = (const float2*)Ug + (size_t)k*(CIN*32) + (oc0 >> 1) + slot;

    float acc[2][16];
    #pragma unroll
    for (int j = 0; j < 2; j++)
        #pragma unroll
        for (int t = 0; t < 16; t++) acc[j][t] = 0.f;

    // prefetch batch 0
    float dreg0 = inb0 ? in[goff0] : 0.f;
    float dreg1 = (has1 && inb1) ? in[goff1] : 0.f;
    float2 un0 = up[0*32], un1 = up[1*32], un2 = up[2*32], un3 = up[3*32];

    float* smd = (float*)sm.ph.d;

    for (int ic0 = 0; ic0 < CIN; ic0 += 4) {
        // stage d (4 ics) — safe: all threads are past bar2 of previous iter
        smd[smoff0] = dreg0;
        if (has1) smd[smoff1] = dreg1;
        __syncthreads();   // d ready; also: everyone done reading prev V

        // V = B^T d B : 4 values per thread (conflict-free stores, stride 1)
        #pragma unroll
        for (int icb = 0; icb < 4; icb++) {
            const float* dd = sm.ph.d[icb];
            float R0 = dd[a00] + sa * dd[a10];
            float R1 = dd[a01] + sa * dd[a11];
            sm.ph.V[icb][k][slot] = R0 + sb * R1;
        }
        __syncthreads();   // V ready; d free

        // prefetch next batch (clamped reload on last iter)
        int icn = (ic0 + 4 < CIN) ? ic0 + 4 : ic0;
        float2 u0 = un0, u1 = un1, u2 = un2, u3 = un3;
        un0 = up[(size_t)(icn+0)*32];
        un1 = up[(size_t)(icn+1)*32];
        un2 = up[(size_t)(icn+2)*32];
        un3 = up[(size_t)(icn+3)*32];
        dreg0 = inb0 ? in[(size_t)icn*HWX + goff0] : 0.f;
        if (has1) dreg1 = inb1 ? in[(size_t)icn*HWX + goff1] : 0.f;

        // core: 4 x 32 FMA, V rows via LDS.128
        #pragma unroll
        for (int icb = 0; icb < 4; icb++) {
            float2 u = (icb == 0) ? u0 : (icb == 1) ? u1 : (icb == 2) ? u2 : u3;
            const float4* vr = (const float4*)sm.ph.V[icb][k];
            #pragma unroll
            for (int w = 0; w < 4; w++) {
                float4 vv = vr[w];
                float tv[4] = {vv.x, vv.y, vv.z, vv.w};
                #pragma unroll
                for (int q = 0; q < 4; q++) {
                    int t = w*4 + q;
                    acc[0][t] = fmaf(u.x, tv[q], acc[0][t]);
                    acc[1][t] = fmaf(u.y, tv[q], acc[1][t]);
                }
            }
        }
    }

    // ---- epilogue: Y = A^T M A, BN, ReLU; single pass (32 oc) ----
    __syncthreads();   // core done; union reuse safe
    #pragma unroll
    for (int j = 0; j < 2; j++)
        #pragma unroll
        for (int t = 0; t < 16; t++)
            sm.M[k][slot*2 + j][t] = acc[j][t];
    __syncthreads();
    #pragma unroll
    for (int q = tid; q < 512; q += 256) {
        int ocq = q >> 4, tile = q & 15;
        int oc = oc0 + ocq;
        float m[16];
        #pragma unroll
        for (int kk = 0; kk < 16; kk++) m[kk] = sm.M[kk][ocq][tile];
        // A^T = [[1,1,1,0],[0,1,-1,-1]]
        float s0[4], s1[4];
        #pragma unroll
        for (int b = 0; b < 4; b++) {
            s0[b] = m[0*4+b] + m[1*4+b] + m[2*4+b];
            s1[b] = m[1*4+b] - m[2*4+b] - m[3*4+b];
        }
        float y00 = s0[0] + s0[1] + s0[2];
        float y01 = s0[1] - s0[2] - s0[3];
        float y10 = s1[0] + s1[1] + s1[2];
        float y11 = s1[1] - s1[2] - s1[3];
        float s = sc[oc], bb = bi[oc];
        int y = oy0 + (tile >> 2)*2;
        int x = ox0 + (tile & 3)*2;
        float* o0 = out + (size_t)oc*HWX + y*WW + x;
        o0[0]      = fmaxf(fmaf(y00, s, bb), 0.f);
        o0[1]      = fmaxf(fmaf(y01, s, bb), 0.f);
        o0[WW]     = fmaxf(fmaf(y10, s, bb), 0.f);
        o0[WW + 1] = fmaxf(fmaf(y11, s, bb), 0.f);
    }
}

// ---------------- hm final conv (64->3) + bias + sigmoid + fused hist1 ----------------
__global__ __launch_bounds__(256)
void conv2_hm_k(const float* __restrict__ W2s, const float* __restrict__ b2s)
{
    const float* __restrict__ in = g_h;
    float* __restrict__ out = g_hm;
    __shared__ float s_in[8][10][34];
    __shared__ float s_w[8][27];
    __shared__ unsigned int s_hist[2048];
    const int tx = threadIdx.x, ty = threadIdx.y;
    const int tid = ty*32 + tx;
    const int x0 = blockIdx.x * 32;
    const int y0 = blockIdx.y * 8;
    float acc[3] = {0.f, 0.f, 0.f};

    for (int i = tid; i < 2048; i += 256) s_hist[i] = 0u;

    for (int ic0 = 0; ic0 < 64; ic0 += 8) {
        for (int i = tid; i < 8*340; i += 256) {
            int icb = i / 340, j = i % 340;
            int r = j / 34, c = j % 34;
            int gy = y0 - 1 + r, gx = x0 - 1 + c;
            float v = 0.f;
            if (gy >= 0 && gy < HH && gx >= 0 && gx < WW)
                v = in[(size_t)(ic0 + icb)*HWX + gy*WW + gx];
            s_in[icb][r][c] = v;
        }
        if (tid < 216) {
            int icb = tid / 27, q = tid % 27;
            int o = q / 9, kk = q % 9;
            s_w[icb][q] = W2s[(o*64 + ic0 + icb)*9 + kk]; // branch 0 base
        }
        __syncthreads();
        #pragma unroll
        for (int icb = 0; icb < 8; icb++) {
            float r9[9];
            #pragma unroll
            for (int ky = 0; ky < 3; ky++)
                #pragma unroll
                for (int kx = 0; kx < 3; kx++) r9[ky*3+kx] = s_in[icb][ty + ky][tx + kx];
            #pragma unroll
            for (int o = 0; o < 3; o++)
                #pragma unroll
                for (int kk = 0; kk < 9; kk++) acc[o] = fmaf(r9[kk], s_w[icb][o*9+kk], acc[o]);
        }
        __syncthreads();
    }
    int x = x0 + tx, y = y0 + ty;
    if (x < WW && y < HH) {
        #pragma unroll
        for (int o = 0; o < 3; o++) {
            float v = acc[o] + b2s[o];
            float s = 1.f / (1.f + expf(-v));
            out[(size_t)o*HWX + y*WW + x] = s;
            atomicAdd(&s_hist[__float_as_uint(s) >> 21], 1u);
        }
    }
    __syncthreads();
    for (int i = tid; i < 2048; i += 256)
        if (s_hist[i]) atomicAdd(&g_hist1[i], s_hist[i]);
}

// ---------------- top-k: 2-level radix-select on float bits + bitonic sort ----------------
__global__ void select1_k() {
    __shared__ unsigned int s[2048];
    int t = threadIdx.x; // 1024
    s[t] = g_hist1[t]; s[t+1024] = g_hist1[t+1024];
    __syncthreads();
    for (int off = 1; off < 2048; off <<= 1) {
        unsigned int v0 = (t + off < 2048) ? s[t + off] : 0u;
        unsigned int v1 = (t + 1024 + off < 2048) ? s[t + 1024 + off] : 0u;
        __syncthreads();
        s[t] += v0; s[t+1024] += v1;
        __syncthreads();
    }
    for (int p = t; p < 2048; p += 1024) {
        if (s[p] >= KTOP && (p == 2047 || s[p+1] < KTOP)) {
            g_T1 = (unsigned int)p;
            g_above1 = (p < 2047) ? s[p+1] : 0u;
        }
    }
}

__global__ void hist2_k() {
    __shared__ unsigned int h[2048];
    int t = threadIdx.x;
    unsigned int T1 = g_T1;
    for (int i = t; i < 2048; i += blockDim.x) h[i] = 0u;
    __syncthreads();
    for (int i = blockIdx.x * blockDim.x + t; i < NHM; i += gridDim.x * blockDim.x) {
        unsigned int bits = __float_as_uint(g_hm[i]);
        if ((bits >> 21) == T1) atomicAdd(&h[(bits >> 10) & 0x7FFu], 1u);
    }
    __syncthreads();
    for (int i = t; i < 2048; i += blockDim.x)
        if (h[i]) atomicAdd(&g_hist2[i], h[i]);
}

__global__ void select2_k() {
    __shared__ unsigned int s[2048];
    int t = threadIdx.x;
    unsigned int need = KTOP - g_above1;
    s[t] = g_hist2[t]; s[t+1024] = g_hist2[t+1024];
    __syncthreads();
    for (int off = 1; off < 2048; off <<= 1) {
        unsigned int v0 = (t + off < 2048) ? s[t + off] : 0u;
        unsigned int v1 = (t + 1024 + off < 2048) ? s[t + 1024 + off] : 0u;
        __syncthreads();
        s[t] += v0; s[t+1024] += v1;
        __syncthreads();
    }
    for (int p = t; p < 2048; p += 1024) {
        if (s[p] >= need && (p == 2047 || s[p+1] < need)) g_T2 = (unsigned int)p;
    }
}

__global__ void compact_k() {
    unsigned int T1 = g_T1, T2 = g_T2;
    for (int i = blockIdx.x * blockDim.x + threadIdx.x; i < NHM; i += gridDim.x * blockDim.x) {
        float v = g_hm[i];
        unsigned int bits = __float_as_uint(v);
        unsigned int b1 = bits >> 21;
        bool take = (b1 > T1) || (b1 == T1 && ((bits >> 10) & 0x7FFu) >= T2);
        if (take) {
            unsigned int pos = atomicAdd(&g_cand_count, 1u);
            if (pos < CANDS) { g_cand_val[pos] = v; g_cand_idx[pos] = i; }
        }
    }
}

// dynamic-size bitonic: sort next-pow2(M) elements only
__global__ void sort_topk_k() {
    __shared__ float sv[CANDS];
    __shared__ int   si[CANDS];
    int t = threadIdx.x; // 1024
    unsigned int M = g_cand_count; if (M > CANDS) M = CANDS;
    int Mp = 512; while (Mp < (int)M) Mp <<= 1;   // 512..4096 (M >= KTOP=500 guaranteed)
    for (int e = t; e < Mp; e += 1024) {
        if (e < (int)M) { sv[e] = g_cand_val[e]; si[e] = g_cand_idx[e]; }
        else            { sv[e] = -1.f;          si[e] = 0x7fffffff; }
    }
    __syncthreads();
    for (int k = 2; k <= Mp; k <<= 1) {
        for (int j = k >> 1; j > 0; j >>= 1) {
            for (int e = t; e < Mp; e += 1024) {
                int p = e ^ j;
                if (p > e) {
                    bool asc = ((e & k) == 0);
                    float va = sv[e], vb = sv[p];
                    int   ia = si[e], ib = si[p];
                    bool b_first = (vb > va) || (vb == va && ib < ia);
                    if (b_first == asc) { sv[e]=vb; sv[p]=va; si[e]=ib; si[p]=ia; }
                }
            }
            __syncthreads();
        }
    }
    if (t < KTOP) { g_topk_val[t] = sv[t]; g_topk_idx[t] = si[t]; }
}

// ---------------- sparse branch eval (branches 1..5 at 500 positions) ----------------
__device__ __forceinline__ float acc_out(const float* sm_in, const float* sm_w, int o, int ic0) {
    int p = o / 64, oc = o % 64, py = p / 3, px = p % 3;
    float part = 0.f;
    #pragma unroll
    for (int icl = 0; icl < 8; icl++) {
        const float* wrow = sm_w + icl*576 + oc*9;
        #pragma unroll
        for (int ky = 0; ky < 3; ky++)
            #pragma unroll
            for (int kx = 0; kx < 3; kx++) {
                int pin = (py + ky)*5 + (px + kx);
                part = fmaf(sm_in[pin*64 + ic0 + icl], wrow[ky*3+kx], part);
            }
    }
    return part;
}

__global__ __launch_bounds__(256)
void sparse_branch_k(const float* __restrict__ W2s, const float* __restrict__ b2s) {
    __shared__ float sm_in[25*64];
    __shared__ float sm_w[8*576];
    __shared__ float sm_h[576];
    int det = blockIdx.x;
    int b = blockIdx.y + 1; // branches 1..5
    int tid = threadIdx.x;
    int idx = g_topk_idx[det];
    int sp = idx % HWX;
    int cy = sp / WW, cx = sp % WW;

    for (int i = tid; i < 1600; i += 256) {
        int p = i / 64, ic = i % 64;
        int gy = cy + p/5 - 2, gx = cx + p%5 - 2;
        float v = 0.f;
        if (gy >= 0 && gy < HH && gx >= 0 && gx < WW)
            v = g_shared[(size_t)ic*HWX + gy*WW + gx];
        sm_in[p*64 + ic] = v;
    }
    __syncthreads();

    float a0 = 0.f, a1 = 0.f, a2 = 0.f;
    for (int c = 0; c < 8; c++) {
        int ic0 = c * 8;
        const float* wb = g_W1t + (size_t)(b*64 + ic0) * 576;
        for (int i = tid; i < 4608; i += 256) sm_w[i] = wb[i];
        __syncthreads();
        a0 += acc_out(sm_in, sm_w, tid,       ic0);
        a1 += acc_out(sm_in, sm_w, tid + 256, ic0);
        if (tid < 64) a2 += acc_out(sm_in, sm_w, tid + 512, ic0);
        __syncthreads();
    }

    // BN + ReLU + zero out-of-image conv1 pixels
    {
        float accs[3] = {a0, a1, a2};
        int os[3] = {tid, tid + 256, tid + 512};
        #pragma unroll
        for (int q = 0; q < 3; q++) {
            int o = os[q];
            if (o < 576) {
                int p = o / 64, oc = o % 64;
                float v = fmaf(accs[q], g_sc1[b*64+oc], g_bi1[b*64+oc]);
                v = fmaxf(v, 0.f);
                int gy = cy + p/3 - 1, gx = cx + p%3 - 1;
                if (gy < 0 || gy >= HH || gx < 0 || gx >= WW) v = 0.f;
                sm_h[p*64 + oc] = v;
            }
        }
    }
    __syncthreads();

    int warp = tid >> 5, lane = tid & 31;
    if (warp < 3) {
        const float* w2 = W2s + (size_t)((b*3 + warp) * 64) * 9;
        float sum = 0.f;
        for (int t2 = lane; t2 < 576; t2 += 32) {
            int oc = t2 / 9, p = t2 % 9;
            sum = fmaf(sm_h[p*64 + oc], w2[t2], sum);
        }
        #pragma unroll
        for (int off = 16; off > 0; off >>= 1)
            sum += __shfl_down_sync(0xFFFFFFFFu, sum, off);
        if (lane == 0)
            g_gather[((b-1)*KTOP + det)*3 + warp] = sum + b2s[b*3 + warp];
    }
}

// ---------------- decode ----------------
__global__ void decode_k(float* __restrict__ out) {
    int k = blockIdx.x * blockDim.x + threadIdx.x;
    if (k >= KTOP) return;
    float s = g_topk_val[k];
    int idx = g_topk_idx[k];
    int cls = idx / HWX;
    int sp  = idx % HWX;
    float ys = (float)(sp / WW);
    float xs = (float)(sp % WW);
    const float* gC = &g_gather[(0*KTOP + k)*3];
    const float* gZ = &g_gather[(1*KTOP + k)*3];
    const float* gD = &g_gather[(2*KTOP + k)*3];
    const float* gR = &g_gather[(3*KTOP + k)*3];
    const float* gI = &g_gather[(4*KTOP + k)*3];
    float xg = (xs + gC[0]) * 0.4f - 75.2f;
    float yg = (ys + gC[1]) * 0.4f - 75.2f;
    float cz = gZ[0];
    float d0 = expf(gD[0]), d1 = expf(gD[1]), d2 = expf(gD[2]);
    float heading = atan2f(gR[1], gR[0]);
    float iou = (gI[0] + 1.f) * 0.5f;
    iou = fminf(fmaxf(iou, 0.f), 1.f);
    const float rect[3] = {0.68f, 0.71f, 0.65f};
    float r = rect[cls];
    float sc = powf(s, 1.f - r) * powf(iou, r);
    if (!(sc > 0.1f)) sc = 0.f;
    out[k*7 + 0] = xg;
    out[k*7 + 1] = yg;
    out[k*7 + 2] = cz;
    out[k*7 + 3] = d0;
    out[k*7 + 4] = d1;
    out[k*7 + 5] = d2;
    out[k*7 + 6] = heading;
    out[KTOP*7 + k] = sc;            // scores at 3500..3999
    out[KTOP*7 + KTOP + k] = (float)cls; // cls at 4000..4499
}

// ---------------- launch ----------------
extern "C" void kernel_launch(void* const* d_in, const int* in_sizes, int n_in,
                              void* d_out, int out_size) {
    const float* x     = (const float*)d_in[0];
    const float* W_sh  = (const float*)d_in[1];
    const float* bn_sh = (const float*)d_in[2];
    const float* W1s   = (const float*)d_in[3];
    const float* bn1s  = (const float*)d_in[4];
    const float* W2s   = (const float*)d_in[5];
    const float* b2s   = (const float*)d_in[6];
    float* out = (float*)d_out;

    setup_k<<<(out_size + 255)/256 > 8 ? (out_size + 255)/256 : 8, 256>>>(bn_sh, bn1s, out, out_size);
    wg_transform_sh_k<<<(64*256 + 255)/256, 256>>>(W_sh);
    wg_transform_w1_k<<<(64*64 + 255)/256, 256>>>(W1s);

    dim3 wgrid(47, 47, 2);
    winograd_k<256, 0><<<wgrid, 256>>>(x);        // shared conv 256->64 (launch #4: ncu target)
    winograd_k<64, 1><<<wgrid, 256>>>(nullptr);   // hm conv1 64->64

    transpose_w1_k<<<(6*64*64*9 + 511)/512, 512>>>(W1s);

    dim3 cgrid(12, 47), cblk(32, 8);
    conv2_hm_k<<<cgrid, cblk>>>(W2s, b2s);

    select1_k<<<1, 1024>>>();
    hist2_k<<<512, 512>>>();
    select2_k<<<1, 1024>>>();
    compact_k<<<512, 512>>>();
    sort_topk_k<<<1, 1024>>>();

    dim3 sgrid(KTOP, 5);
    sparse_branch_k<<<sgrid, 256>>>(W2s, b2s);
    decode_k<<<2, 256>>>(out);
}

// round 13
// speedup vs baseline: 1.1392x; 1.1392x over previous
#include <cuda_runtime.h>

#define HH 376
#define WW 376
#define HWX (HH*WW)          // 141376
#define NHM (3*HWX)          // 424128
#define KTOP 500
#define CANDS 4096

// ---------------- scratch (device globals: no allocation allowed) ----------------
__device__ float g_shared[64 * HWX];     // shared conv output (BN+ReLU)
__device__ float g_h[64 * HWX];          // hm branch conv1 output
__device__ float g_hm[3 * HWX];          // sigmoid heatmap
__device__ float g_Ush[16 * 256 * 64];   // winograd weights shared conv: [k16][ic][oc]
__device__ float g_U1[16 * 64 * 64];     // winograd weights hm conv1 (branch 0)
__device__ float g_W1t[6 * 64 * 64 * 9]; // [b][ic][oc][9] (for sparse path)
__device__ float g_sc_sh[64], g_bi_sh[64];
__device__ float g_sc1[6 * 64], g_bi1[6 * 64];
__device__ unsigned int g_hist1[2048], g_hist2[2048];
__device__ unsigned int g_T1, g_above1, g_T2;
__device__ unsigned int g_cand_count;
__device__ float g_cand_val[CANDS];
__device__ int   g_cand_idx[CANDS];
__device__ float g_topk_val[512];
__device__ int   g_topk_idx[512];
__device__ float g_gather[5 * KTOP * 3]; // [branch-1][det][3]

// ---------------- merged setup: zero hists/out + BN prep ----------------
__global__ void setup_k(const float* __restrict__ bn_sh, const float* __restrict__ bn1s,
                        float* __restrict__ out, int out_n) {
    int i = blockIdx.x * blockDim.x + threadIdx.x;
    if (i < 2048) { g_hist1[i] = 0u; g_hist2[i] = 0u; }
    if (i == 0) g_cand_count = 0u;
    if (i < out_n) out[i] = 0.f;
    if (i < 64) {
        int c = i;
        float g = bn_sh[0*64+c], b = bn_sh[1*64+c], m = bn_sh[2*64+c], v = bn_sh[3*64+c];
        float sc = g * rsqrtf(v + 1e-5f);
        g_sc_sh[c] = sc; g_bi_sh[c] = b - m * sc;
        for (int br = 0; br < 6; br++) {
            const float* p = bn1s + br * 4 * 64;
            float g1 = p[0*64+c], b1 = p[1*64+c], m1 = p[2*64+c], v1 = p[3*64+c];
            float s1 = g1 * rsqrtf(v1 + 1e-5f);
            g_sc1[br*64+c] = s1; g_bi1[br*64+c] = b1 - m1 * s1;
        }
    }
}

// ---------------- Winograd weight transform: U = G g G^T ----------------
// G = [[1,0,0],[.5,.5,.5],[.5,-.5,.5],[0,0,1]]
__device__ __forceinline__ void wg_fill(const float* __restrict__ g9, float u[4][4]) {
    float t[4][3];
    #pragma unroll
    for (int c = 0; c < 3; c++) {
        float g0 = g9[0*3+c], g1 = g9[1*3+c], g2 = g9[2*3+c];
        t[0][c] = g0;
        t[1][c] = 0.5f*(g0 + g1 + g2);
        t[2][c] = 0.5f*(g0 - g1 + g2);
        t[3][c] = g2;
    }
    #pragma unroll
    for (int r = 0; r < 4; r++) {
        float a = t[r][0], b = t[r][1], c = t[r][2];
        u[r][0] = a;
        u[r][1] = 0.5f*(a + b + c);
        u[r][2] = 0.5f*(a - b + c);
        u[r][3] = c;
    }
}

// merged: W_sh [oc64][ic256][9] -> g_Ush [k16][ic][oc]  (i < 16384)
//         W1s branch0 [oc64][ic64][9] -> g_U1 [k16][ic][oc]  (i >= 16384)
__global__ void wg_transform_all_k(const float* __restrict__ wsh, const float* __restrict__ w1) {
    int i = blockIdx.x * blockDim.x + threadIdx.x;
    if (i < 64*256) {
        int ic = i % 256, oc = i / 256;
        float u[4][4];
        wg_fill(wsh + (size_t)i*9, u);
        #pragma unroll
        for (int r = 0; r < 4; r++)
            #pragma unroll
            for (int c = 0; c < 4; c++)
                g_Ush[(r*4+c)*(256*64) + ic*64 + oc] = u[r][c];
    } else if (i < 64*256 + 64*64) {
        int j = i - 64*256;
        int ic = j % 64, oc = j / 64;
        float u[4][4];
        wg_fill(w1 + (size_t)j*9, u);
        #pragma unroll
        for (int r = 0; r < 4; r++)
            #pragma unroll
            for (int c = 0; c < 4; c++)
                g_U1[(r*4+c)*(64*64) + ic*64 + oc] = u[r][c];
    }
}

// W1s [b][oc64][ic64][9] -> g_W1t [b][ic][oc][9]  (sparse path)
__global__ void transpose_w1_k(const float* __restrict__ w) {
    int i = blockIdx.x * blockDim.x + threadIdx.x;
    if (i >= 6*64*64*9) return;
    int k = i % 9; int r = i / 9; int ic = r % 64; r /= 64; int oc = r % 64; int b = r / 64;
    g_W1t[(((b*64 + ic)*64) + oc)*9 + k] = w[i];
}

// ---------------- Winograd F(2x2,3x3) conv + BN + ReLU (Cout=64) ----------------
// R11-proven config: 2 CTAs/SM, 64 oc/block, register-resident float4 U double-buffer.
template<int CIN, int MODE>
__global__ __launch_bounds__(256, 2)
void winograd_k(const float* __restrict__ xin)
{
    const float* __restrict__ in = (MODE == 0) ? xin : g_shared;
    const float* __restrict__ Ug = (MODE == 0) ? g_Ush : g_U1;
    const float* __restrict__ sc = (MODE == 0) ? g_sc_sh : g_sc1;
    const float* __restrict__ bi = (MODE == 0) ? g_bi_sh : g_bi1;
    float* __restrict__ out      = (MODE == 0) ? g_shared : g_h;

    __shared__ union {
        struct {
            float V[4][16][16];   // [icb][k][tile] rows contiguous (LDS.128 in core)
            float d[4][112];      // [icb][r*11+c], 110 used
        } ph;
        float M[16][32][16];      // epilogue exchange: [k][oc-half][tile]
    } sm;

    const int tid = threadIdx.x;
    const int ox0 = blockIdx.x * 8, oy0 = blockIdx.y * 8;
    const int k = tid >> 4;      // transform point 0..15 (V + core)
    const int slot = tid & 15;   // V-phase tile / core oc-group

    int goff0 = 0, goff1 = 0, smoff0 = 0, smoff1 = 0;
    bool inb0 = false, inb1 = false;
    {
        int p = tid % 100, icb = tid / 100;
        int lr = p / 10, lc = p % 10;
        int gy = oy0 - 1 + lr, gx = ox0 - 1 + lc;
        inb0 = (gy >= 0 && gy < HH && gx >= 0 && gx < WW);
        goff0 = icb*HWX + gy*WW + gx;
        smoff0 = icb*112 + lr*11 + lc;
    }
    const bool has1 = (tid < 144);
    if (has1) {
        int i = tid + 256;
        int p = i % 100, icb = i / 100;
        int lr = p / 10, lc = p % 10;
        int gy = oy0 - 1 + lr, gx = ox0 - 1 + lc;
        inb1 = (gy >= 0 && gy < HH && gx >= 0 && gx < WW);
        goff1 = icb*HWX + gy*WW + gx;
        smoff1 = icb*112 + lr*11 + lc;
    }

    const int va = k >> 2, vb = k & 3;
    const int ia0 = (va == 0) ? 0 : ((va == 2) ? 2 : 1);
    const int ia1 = (va < 2) ? 2 : ((va == 2) ? 1 : 3);
    const float sa = (va == 1) ? 1.f : -1.f;
    const int ib0 = (vb == 0) ? 0 : ((vb == 2) ? 2 : 1);
    const int ib1 = (vb < 2) ? 2 : ((vb == 2) ? 1 : 3);
    const float sb = (vb == 1) ? 1.f : -1.f;
    const int r0 = (slot >> 2)*2 + ia0, r1 = (slot >> 2)*2 + ia1;
    const int c0 = (slot & 3)*2 + ib0,  c1 = (slot & 3)*2 + ib1;
    const int a00 = r0*11 + c0, a01 = r0*11 + c1;
    const int a10 = r1*11 + c0, a11 = r1*11 + c1;

    const float4* up = (const float4*)Ug + (size_t)k*(CIN*16) + slot;

    float acc[4][16];
    #pragma unroll
    for (int j = 0; j < 4; j++)
        #pragma unroll
        for (int t = 0; t < 16; t++) acc[j][t] = 0.f;

    float dreg0 = inb0 ? in[goff0] : 0.f;
    float dreg1 = (has1 && inb1) ? in[goff1] : 0.f;
    float4 un0 = up[0*16], un1 = up[1*16], un2 = up[2*16], un3 = up[3*16];

    float* smd = (float*)sm.ph.d;

    for (int ic0 = 0; ic0 < CIN; ic0 += 4) {
        smd[smoff0] = dreg0;
        if (has1) smd[smoff1] = dreg1;
        __syncthreads();   // d ready; also: everyone done reading prev V

        #pragma unroll
        for (int icb = 0; icb < 4; icb++) {
            const float* dd = sm.ph.d[icb];
            float R0 = dd[a00] + sa * dd[a10];
            float R1 = dd[a01] + sa * dd[a11];
            sm.ph.V[icb][k][slot] = R0 + sb * R1;
        }
        __syncthreads();   // V ready; d free

        int icn = (ic0 + 4 < CIN) ? ic0 + 4 : ic0;
        float4 u0 = un0, u1 = un1, u2 = un2, u3 = un3;
        un0 = up[(size_t)(icn+0)*16];
        un1 = up[(size_t)(icn+1)*16];
        un2 = up[(size_t)(icn+2)*16];
        un3 = up[(size_t)(icn+3)*16];
        dreg0 = inb0 ? in[(size_t)icn*HWX + goff0] : 0.f;
        if (has1) dreg1 = inb1 ? in[(size_t)icn*HWX + goff1] : 0.f;

        #pragma unroll
        for (int icb = 0; icb < 4; icb++) {
            float4 u = (icb == 0) ? u0 : (icb == 1) ? u1 : (icb == 2) ? u2 : u3;
            const float4* vr = (const float4*)sm.ph.V[icb][k];
            #pragma unroll
            for (int w = 0; w < 4; w++) {
                float4 vv = vr[w];
                float tv[4] = {vv.x, vv.y, vv.z, vv.w};
                #pragma unroll
                for (int q = 0; q < 4; q++) {
                    int t = w*4 + q;
                    acc[0][t] = fmaf(u.x, tv[q], acc[0][t]);
                    acc[1][t] = fmaf(u.y, tv[q], acc[1][t]);
                    acc[2][t] = fmaf(u.z, tv[q], acc[2][t]);
                    acc[3][t] = fmaf(u.w, tv[q], acc[3][t]);
                }
            }
        }
    }

    #pragma unroll
    for (int h = 0; h < 2; h++) {
        __syncthreads();
        if ((slot >> 3) == h) {
            int ocl = (slot & 7) * 4;
            #pragma unroll
            for (int j = 0; j < 4; j++)
                #pragma unroll
                for (int t = 0; t < 16; t++)
                    sm.M[k][ocl + j][t] = acc[j][t];
        }
        __syncthreads();
        #pragma unroll
        for (int q = tid; q < 512; q += 256) {
            int ocq = q >> 4, tile = q & 15;
            int oc = h*32 + ocq;
            float m[16];
            #pragma unroll
            for (int kk = 0; kk < 16; kk++) m[kk] = sm.M[kk][ocq][tile];
            float s0[4], s1[4];
            #pragma unroll
            for (int b = 0; b < 4; b++) {
                s0[b] = m[0*4+b] + m[1*4+b] + m[2*4+b];
                s1[b] = m[1*4+b] - m[2*4+b] - m[3*4+b];
            }
            float y00 = s0[0] + s0[1] + s0[2];
            float y01 = s0[1] - s0[2] - s0[3];
            float y10 = s1[0] + s1[1] + s1[2];
            float y11 = s1[1] - s1[2] - s1[3];
            float s = sc[oc], bb = bi[oc];
            int y = oy0 + (tile >> 2)*2;
            int x = ox0 + (tile & 3)*2;
            float* o0 = out + (size_t)oc*HWX + y*WW + x;
            o0[0]      = fmaxf(fmaf(y00, s, bb), 0.f);
            o0[1]      = fmaxf(fmaf(y01, s, bb), 0.f);
            o0[WW]     = fmaxf(fmaf(y10, s, bb), 0.f);
            o0[WW + 1] = fmaxf(fmaf(y11, s, bb), 0.f);
        }
    }
}

// ---------------- hm final conv (64->3) + bias + sigmoid + fused hist1, IC_BATCH=16 ----------------
__global__ __launch_bounds__(256)
void conv2_hm_k(const float* __restrict__ W2s, const float* __restrict__ b2s)
{
    const float* __restrict__ in = g_h;
    float* __restrict__ out = g_hm;
    __shared__ float s_in[16][10][34];
    __shared__ float s_w[16][27];
    __shared__ unsigned int s_hist[2048];
    const int tx = threadIdx.x, ty = threadIdx.y;
    const int tid = ty*32 + tx;
    const int x0 = blockIdx.x * 32;
    const int y0 = blockIdx.y * 8;
    float acc[3] = {0.f, 0.f, 0.f};

    for (int i = tid; i < 2048; i += 256) s_hist[i] = 0u;

    for (int ic0 = 0; ic0 < 64; ic0 += 16) {
        for (int i = tid; i < 16*340; i += 256) {
            int icb = i / 340, j = i % 340;
            int r = j / 34, c = j % 34;
            int gy = y0 - 1 + r, gx = x0 - 1 + c;
            float v = 0.f;
            if (gy >= 0 && gy < HH && gx >= 0 && gx < WW)
                v = in[(size_t)(ic0 + icb)*HWX + gy*WW + gx];
            s_in[icb][r][c] = v;
        }
        for (int i = tid; i < 16*27; i += 256) {
            int icb = i / 27, q = i % 27;
            int o = q / 9, kk = q % 9;
            s_w[icb][q] = W2s[(o*64 + ic0 + icb)*9 + kk]; // branch 0 base
        }
        __syncthreads();
        #pragma unroll
        for (int icb = 0; icb < 16; icb++) {
            float r9[9];
            #pragma unroll
            for (int ky = 0; ky < 3; ky++)
                #pragma unroll
                for (int kx = 0; kx < 3; kx++) r9[ky*3+kx] = s_in[icb][ty + ky][tx + kx];
            #pragma unroll
            for (int o = 0; o < 3; o++)
                #pragma unroll
                for (int kk = 0; kk < 9; kk++) acc[o] = fmaf(r9[kk], s_w[icb][o*9+kk], acc[o]);
        }
        __syncthreads();
    }
    int x = x0 + tx, y = y0 + ty;
    if (x < WW && y < HH) {
        #pragma unroll
        for (int o = 0; o < 3; o++) {
            float v = acc[o] + b2s[o];
            float s = 1.f / (1.f + expf(-v));
            out[(size_t)o*HWX + y*WW + x] = s;
            atomicAdd(&s_hist[__float_as_uint(s) >> 21], 1u);
        }
    }
    __syncthreads();
    for (int i = tid; i < 2048; i += 256)
        if (s_hist[i]) atomicAdd(&g_hist1[i], s_hist[i]);
}

// ---------------- top-k: 2-level radix-select on float bits + bitonic sort ----------------
__global__ void select1_k() {
    __shared__ unsigned int s[2048];
    int t = threadIdx.x; // 1024
    s[t] = g_hist1[t]; s[t+1024] = g_hist1[t+1024];
    __syncthreads();
    for (int off = 1; off < 2048; off <<= 1) {
        unsigned int v0 = (t + off < 2048) ? s[t + off] : 0u;
        unsigned int v1 = (t + 1024 + off < 2048) ? s[t + 1024 + off] : 0u;
        __syncthreads();
        s[t] += v0; s[t+1024] += v1;
        __syncthreads();
    }
    for (int p = t; p < 2048; p += 1024) {
        if (s[p] >= KTOP && (p == 2047 || s[p+1] < KTOP)) {
            g_T1 = (unsigned int)p;
            g_above1 = (p < 2047) ? s[p+1] : 0u;
        }
    }
}

__global__ void hist2_k() {
    __shared__ unsigned int h[2048];
    int t = threadIdx.x;
    unsigned int T1 = g_T1;
    for (int i = t; i < 2048; i += blockDim.x) h[i] = 0u;
    __syncthreads();
    for (int i = blockIdx.x * blockDim.x + t; i < NHM; i += gridDim.x * blockDim.x) {
        unsigned int bits = __float_as_uint(g_hm[i]);
        if ((bits >> 21) == T1) atomicAdd(&h[(bits >> 10) & 0x7FFu], 1u);
    }
    __syncthreads();
    for (int i = t; i < 2048; i += blockDim.x)
        if (h[i]) atomicAdd(&g_hist2[i], h[i]);
}

__global__ void select2_k() {
    __shared__ unsigned int s[2048];
    int t = threadIdx.x;
    unsigned int need = KTOP - g_above1;
    s[t] = g_hist2[t]; s[t+1024] = g_hist2[t+1024];
    __syncthreads();
    for (int off = 1; off < 2048; off <<= 1) {
        unsigned int v0 = (t + off < 2048) ? s[t + off] : 0u;
        unsigned int v1 = (t + 1024 + off < 2048) ? s[t + 1024 + off] : 0u;
        __syncthreads();
        s[t] += v0; s[t+1024] += v1;
        __syncthreads();
    }
    for (int p = t; p < 2048; p += 1024) {
        if (s[p] >= need && (p == 2047 || s[p+1] < need)) g_T2 = (unsigned int)p;
    }
}

__global__ void compact_k() {
    unsigned int T1 = g_T1, T2 = g_T2;
    for (int i = blockIdx.x * blockDim.x + threadIdx.x; i < NHM; i += gridDim.x * blockDim.x) {
        float v = g_hm[i];
        unsigned int bits = __float_as_uint(v);
        unsigned int b1 = bits >> 21;
        bool take = (b1 > T1) || (b1 == T1 && ((bits >> 10) & 0x7FFu) >= T2);
        if (take) {
            unsigned int pos = atomicAdd(&g_cand_count, 1u);
            if (pos < CANDS) { g_cand_val[pos] = v; g_cand_idx[pos] = i; }
        }
    }
}

// dynamic-size bitonic: sort next-pow2(M) elements only
__global__ void sort_topk_k() {
    __shared__ float sv[CANDS];
    __shared__ int   si[CANDS];
    int t = threadIdx.x; // 1024
    unsigned int M = g_cand_count; if (M > CANDS) M = CANDS;
    int Mp = 512; while (Mp < (int)M) Mp <<= 1;   // 512..4096 (M >= KTOP=500 guaranteed)
    for (int e = t; e < Mp; e += 1024) {
        if (e < (int)M) { sv[e] = g_cand_val[e]; si[e] = g_cand_idx[e]; }
        else            { sv[e] = -1.f;          si[e] = 0x7fffffff; }
    }
    __syncthreads();
    for (int k = 2; k <= Mp; k <<= 1) {
        for (int j = k >> 1; j > 0; j >>= 1) {
            for (int e = t; e < Mp; e += 1024) {
                int p = e ^ j;
                if (p > e) {
                    bool asc = ((e & k) == 0);
                    float va = sv[e], vb = sv[p];
                    int   ia = si[e], ib = si[p];
                    bool b_first = (vb > va) || (vb == va && ib < ia);
                    if (b_first == asc) { sv[e]=vb; sv[p]=va; si[e]=ib; si[p]=ia; }
                }
            }
            __syncthreads();
        }
    }
    if (t < KTOP) { g_topk_val[t] = sv[t]; g_topk_idx[t] = si[t]; }
}

// ---------------- sparse branch eval: 2 dets per block (branches 1..5) ----------------
__device__ __forceinline__ float acc_out2(const float* sm_in, const float* sm_w, int o, int ic0) {
    int p = o / 64, oc = o % 64, py = p / 3, px = p % 3;
    float part = 0.f;
    #pragma unroll
    for (int icl = 0; icl < 8; icl++) {
        const float* wrow = sm_w + icl*576 + oc*9;
        #pragma unroll
        for (int ky = 0; ky < 3; ky++)
            #pragma unroll
            for (int kx = 0; kx < 3; kx++) {
                int pin = (py + ky)*5 + (px + kx);
                part = fmaf(sm_in[pin*64 + ic0 + icl], wrow[ky*3+kx], part);
            }
    }
    return part;
}

__global__ __launch_bounds__(256)
void sparse_branch_k(const float* __restrict__ W2s, const float* __restrict__ b2s) {
    __shared__ float sm_in[2][25*64];
    __shared__ float sm_w[8*576];
    __shared__ float sm_h[2][576];
    int det0 = blockIdx.x * 2;
    int b = blockIdx.y + 1; // branches 1..5
    int tid = threadIdx.x;

    int cy[2], cx[2];
    #pragma unroll
    for (int d = 0; d < 2; d++) {
        int sp = g_topk_idx[det0 + d] % HWX;
        cy[d] = sp / WW; cx[d] = sp % WW;
    }

    for (int i = tid; i < 3200; i += 256) {
        int d = i / 1600, j = i % 1600;
        int p = j / 64, ic = j % 64;
        int gy = cy[d] + p/5 - 2, gx = cx[d] + p%5 - 2;
        float v = 0.f;
        if (gy >= 0 && gy < HH && gx >= 0 && gx < WW)
            v = g_shared[(size_t)ic*HWX + gy*WW + gx];
        sm_in[d][p*64 + ic] = v;
    }
    __syncthreads();

    float a0[2] = {0.f, 0.f}, a1[2] = {0.f, 0.f}, a2[2] = {0.f, 0.f};
    for (int c = 0; c < 8; c++) {
        int ic0 = c * 8;
        const float* wb = g_W1t + (size_t)(b*64 + ic0) * 576;
        for (int i = tid; i < 4608; i += 256) sm_w[i] = wb[i];
        __syncthreads();
        #pragma unroll
        for (int d = 0; d < 2; d++) {
            a0[d] += acc_out2(sm_in[d], sm_w, tid,       ic0);
            a1[d] += acc_out2(sm_in[d], sm_w, tid + 256, ic0);
            if (tid < 64) a2[d] += acc_out2(sm_in[d], sm_w, tid + 512, ic0);
        }
        __syncthreads();
    }

    // BN + ReLU + zero out-of-image conv1 pixels
    #pragma unroll
    for (int d = 0; d < 2; d++) {
        float accs[3] = {a0[d], a1[d], a2[d]};
        int os[3] = {tid, tid + 256, tid + 512};
        #pragma unroll
        for (int q = 0; q < 3; q++) {
            int o = os[q];
            if (o < 576) {
                int p = o / 64, oc = o % 64;
                float v = fmaf(accs[q], g_sc1[b*64+oc], g_bi1[b*64+oc]);
                v = fmaxf(v, 0.f);
                int gy = cy[d] + p/3 - 1, gx = cx[d] + p%3 - 1;
                if (gy < 0 || gy >= HH || gx < 0 || gx >= WW) v = 0.f;
                sm_h[d][p*64 + oc] = v;
            }
        }
    }
    __syncthreads();

    int warp = tid >> 5, lane = tid & 31;
    if (warp < 6) {
        int d = warp / 3, o = warp % 3;
        const float* w2 = W2s + (size_t)((b*3 + o) * 64) * 9;
        float sum = 0.f;
        for (int t2 = lane; t2 < 576; t2 += 32) {
            int oc = t2 / 9, p = t2 % 9;
            sum = fmaf(sm_h[d][p*64 + oc], w2[t2], sum);
        }
        #pragma unroll
        for (int off = 16; off > 0; off >>= 1)
            sum += __shfl_down_sync(0xFFFFFFFFu, sum, off);
        if (lane == 0)
            g_gather[((b-1)*KTOP + det0 + d)*3 + o] = sum + b2s[b*3 + o];
    }
}

// ---------------- decode ----------------
__global__ void decode_k(float* __restrict__ out) {
    int k = blockIdx.x * blockDim.x + threadIdx.x;
    if (k >= KTOP) return;
    float s = g_topk_val[k];
    int idx = g_topk_idx[k];
    int cls = idx / HWX;
    int sp  = idx % HWX;
    float ys = (float)(sp / WW);
    float xs = (float)(sp % WW);
    const float* gC = &g_gather[(0*KTOP + k)*3];
    const float* gZ = &g_gather[(1*KTOP + k)*3];
    const float* gD = &g_gather[(2*KTOP + k)*3];
    const float* gR = &g_gather[(3*KTOP + k)*3];
    const float* gI = &g_gather[(4*KTOP + k)*3];
    float xg = (xs + gC[0]) * 0.4f - 75.2f;
    float yg = (ys + gC[1]) * 0.4f - 75.2f;
    float cz = gZ[0];
    float d0 = expf(gD[0]), d1 = expf(gD[1]), d2 = expf(gD[2]);
    float heading = atan2f(gR[1], gR[0]);
    float iou = (gI[0] + 1.f) * 0.5f;
    iou = fminf(fmaxf(iou, 0.f), 1.f);
    const float rect[3] = {0.68f, 0.71f, 0.65f};
    float r = rect[cls];
    float sc = powf(s, 1.f - r) * powf(iou, r);
    if (!(sc > 0.1f)) sc = 0.f;
    out[k*7 + 0] = xg;
    out[k*7 + 1] = yg;
    out[k*7 + 2] = cz;
    out[k*7 + 3] = d0;
    out[k*7 + 4] = d1;
    out[k*7 + 5] = d2;
    out[k*7 + 6] = heading;
    out[KTOP*7 + k] = sc;            // scores at 3500..3999
    out[KTOP*7 + KTOP + k] = (float)cls; // cls at 4000..4499
}

// ---------------- launch ----------------
extern "C" void kernel_launch(void* const* d_in, const int* in_sizes, int n_in,
                              void* d_out, int out_size) {
    const float* x     = (const float*)d_in[0];
    const float* W_sh  = (const float*)d_in[1];
    const float* bn_sh = (const float*)d_in[2];
    const float* W1s   = (const float*)d_in[3];
    const float* bn1s  = (const float*)d_in[4];
    const float* W2s   = (const float*)d_in[5];
    const float* b2s   = (const float*)d_in[6];
    float* out = (float*)d_out;

    setup_k<<<(out_size + 255)/256 > 8 ? (out_size + 255)/256 : 8, 256>>>(bn_sh, bn1s, out, out_size);
    wg_transform_all_k<<<(64*256 + 64*64 + 255)/256, 256>>>(W_sh, W1s);

    dim3 wgrid(47, 47);
    winograd_k<256, 0><<<wgrid, 256>>>(x);        // shared conv 256->64
    winograd_k<64, 1><<<wgrid, 256>>>(nullptr);   // hm conv1 64->64

    transpose_w1_k<<<(6*64*64*9 + 511)/512, 512>>>(W1s);

    dim3 cgrid(12, 47), cblk(32, 8);
    conv2_hm_k<<<cgrid, cblk>>>(W2s, b2s);

    select1_k<<<1, 1024>>>();
    hist2_k<<<512, 512>>>();
    select2_k<<<1, 1024>>>();
    compact_k<<<512, 512>>>();
    sort_topk_k<<<1, 1024>>>();

    dim3 sgrid(KTOP/2, 5);
    sparse_branch_k<<<sgrid, 256>>>(W2s, b2s);
    decode_k<<<2, 256>>>(out);
}

// round 14
// speedup vs baseline: 1.1665x; 1.0239x over previous
#include <cuda_runtime.h>

#define HH 376
#define WW 376
#define HWX (HH*WW)          // 141376
#define NHM (3*HWX)          // 424128
#define KTOP 500
#define CANDS 4096

// ---------------- scratch (device globals: no allocation allowed) ----------------
__device__ float g_shared[64 * HWX];     // shared conv output (BN+ReLU)
__device__ float g_h[64 * HWX];          // hm branch conv1 output
__device__ float g_hm[3 * HWX];          // sigmoid heatmap
__device__ float g_Ush[16 * 256 * 64];   // winograd weights shared conv: [k16][ic][oc]
__device__ float g_U1[16 * 64 * 64];     // winograd weights hm conv1 (branch 0)
__device__ float g_W1t[6 * 64 * 64 * 9]; // [b][ic][oc][9] (for sparse path)
__device__ float g_sc_sh[64], g_bi_sh[64];
__device__ float g_sc1[6 * 64], g_bi1[6 * 64];
__device__ unsigned int g_hist1[2048], g_hist2[2048];
__device__ unsigned int g_T1, g_above1, g_T2;
__device__ unsigned int g_cand_count;
__device__ float g_cand_val[CANDS];
__device__ int   g_cand_idx[CANDS];
__device__ float g_topk_val[512];
__device__ int   g_topk_idx[512];
__device__ float g_gather[5 * KTOP * 3]; // [branch-1][det][3]

// ---------------- merged setup: zero hists/out + BN prep ----------------
__global__ void setup_k(const float* __restrict__ bn_sh, const float* __restrict__ bn1s,
                        float* __restrict__ out, int out_n) {
    int i = blockIdx.x * blockDim.x + threadIdx.x;
    if (i < 2048) { g_hist1[i] = 0u; g_hist2[i] = 0u; }
    if (i == 0) g_cand_count = 0u;
    if (i < out_n) out[i] = 0.f;
    if (i < 64) {
        int c = i;
        float g = bn_sh[0*64+c], b = bn_sh[1*64+c], m = bn_sh[2*64+c], v = bn_sh[3*64+c];
        float sc = g * rsqrtf(v + 1e-5f);
        g_sc_sh[c] = sc; g_bi_sh[c] = b - m * sc;
        for (int br = 0; br < 6; br++) {
            const float* p = bn1s + br * 4 * 64;
            float g1 = p[0*64+c], b1 = p[1*64+c], m1 = p[2*64+c], v1 = p[3*64+c];
            float s1 = g1 * rsqrtf(v1 + 1e-5f);
            g_sc1[br*64+c] = s1; g_bi1[br*64+c] = b1 - m1 * s1;
        }
    }
}

// ---------------- Winograd weight transform: U = G g G^T ----------------
// G = [[1,0,0],[.5,.5,.5],[.5,-.5,.5],[0,0,1]]
__device__ __forceinline__ void wg_fill(const float* __restrict__ g9, float u[4][4]) {
    float t[4][3];
    #pragma unroll
    for (int c = 0; c < 3; c++) {
        float g0 = g9[0*3+c], g1 = g9[1*3+c], g2 = g9[2*3+c];
        t[0][c] = g0;
        t[1][c] = 0.5f*(g0 + g1 + g2);
        t[2][c] = 0.5f*(g0 - g1 + g2);
        t[3][c] = g2;
    }
    #pragma unroll
    for (int r = 0; r < 4; r++) {
        float a = t[r][0], b = t[r][1], c = t[r][2];
        u[r][0] = a;
        u[r][1] = 0.5f*(a + b + c);
        u[r][2] = 0.5f*(a - b + c);
        u[r][3] = c;
    }
}

// merged: W_sh [oc64][ic256][9] -> g_Ush ; W1s branch0 -> g_U1
__global__ void wg_transform_all_k(const float* __restrict__ wsh, const float* __restrict__ w1) {
    int i = blockIdx.x * blockDim.x + threadIdx.x;
    if (i < 64*256) {
        int ic = i % 256, oc = i / 256;
        float u[4][4];
        wg_fill(wsh + (size_t)i*9, u);
        #pragma unroll
        for (int r = 0; r < 4; r++)
            #pragma unroll
            for (int c = 0; c < 4; c++)
                g_Ush[(r*4+c)*(256*64) + ic*64 + oc] = u[r][c];
    } else if (i < 64*256 + 64*64) {
        int j = i - 64*256;
        int ic = j % 64, oc = j / 64;
        float u[4][4];
        wg_fill(w1 + (size_t)j*9, u);
        #pragma unroll
        for (int r = 0; r < 4; r++)
            #pragma unroll
            for (int c = 0; c < 4; c++)
                g_U1[(r*4+c)*(64*64) + ic*64 + oc] = u[r][c];
    }
}

// W1s [b][oc64][ic64][9] -> g_W1t [b][ic][oc][9]  (sparse path)
__global__ void transpose_w1_k(const float* __restrict__ w) {
    int i = blockIdx.x * blockDim.x + threadIdx.x;
    if (i >= 6*64*64*9) return;
    int k = i % 9; int r = i / 9; int ic = r % 64; r /= 64; int oc = r % 64; int b = r / 64;
    g_W1t[(((b*64 + ic)*64) + oc)*9 + k] = w[i];
}

// ---------------- Winograd F(2x2,3x3) conv + BN + ReLU (Cout=64) ----------------
// R11-proven config: 2 CTAs/SM, 64 oc/block, register-resident float4 U double-buffer.
template<int CIN, int MODE>
__global__ __launch_bounds__(256, 2)
void winograd_k(const float* __restrict__ xin)
{
    const float* __restrict__ in = (MODE == 0) ? xin : g_shared;
    const float* __restrict__ Ug = (MODE == 0) ? g_Ush : g_U1;
    const float* __restrict__ sc = (MODE == 0) ? g_sc_sh : g_sc1;
    const float* __restrict__ bi = (MODE == 0) ? g_bi_sh : g_bi1;
    float* __restrict__ out      = (MODE == 0) ? g_shared : g_h;

    __shared__ union {
        struct {
            float V[4][16][16];   // [icb][k][tile] rows contiguous (LDS.128 in core)
            float d[4][112];      // [icb][r*11+c], 110 used
        } ph;
        float M[16][32][16];      // epilogue exchange: [k][oc-half][tile]
    } sm;

    const int tid = threadIdx.x;
    const int ox0 = blockIdx.x * 8, oy0 = blockIdx.y * 8;
    const int k = tid >> 4;      // transform point 0..15 (V + core)
    const int slot = tid & 15;   // V-phase tile / core oc-group

    int goff0 = 0, goff1 = 0, smoff0 = 0, smoff1 = 0;
    bool inb0 = false, inb1 = false;
    {
        int p = tid % 100, icb = tid / 100;
        int lr = p / 10, lc = p % 10;
        int gy = oy0 - 1 + lr, gx = ox0 - 1 + lc;
        inb0 = (gy >= 0 && gy < HH && gx >= 0 && gx < WW);
        goff0 = icb*HWX + gy*WW + gx;
        smoff0 = icb*112 + lr*11 + lc;
    }
    const bool has1 = (tid < 144);
    if (has1) {
        int i = tid + 256;
        int p = i % 100, icb = i / 100;
        int lr = p / 10, lc = p % 10;
        int gy = oy0 - 1 + lr, gx = ox0 - 1 + lc;
        inb1 = (gy >= 0 && gy < HH && gx >= 0 && gx < WW);
        goff1 = icb*HWX + gy*WW + gx;
        smoff1 = icb*112 + lr*11 + lc;
    }

    const int va = k >> 2, vb = k & 3;
    const int ia0 = (va == 0) ? 0 : ((va == 2) ? 2 : 1);
    const int ia1 = (va < 2) ? 2 : ((va == 2) ? 1 : 3);
    const float sa = (va == 1) ? 1.f : -1.f;
    const int ib0 = (vb == 0) ? 0 : ((vb == 2) ? 2 : 1);
    const int ib1 = (vb < 2) ? 2 : ((vb == 2) ? 1 : 3);
    const float sb = (vb == 1) ? 1.f : -1.f;
    const int r0 = (slot >> 2)*2 + ia0, r1 = (slot >> 2)*2 + ia1;
    const int c0 = (slot & 3)*2 + ib0,  c1 = (slot & 3)*2 + ib1;
    const int a00 = r0*11 + c0, a01 = r0*11 + c1;
    const int a10 = r1*11 + c0, a11 = r1*11 + c1;

    const float4* up = (const float4*)Ug + (size_t)k*(CIN*16) + slot;

    float acc[4][16];
    #pragma unroll
    for (int j = 0; j < 4; j++)
        #pragma unroll
        for (int t = 0; t < 16; t++) acc[j][t] = 0.f;

    float dreg0 = inb0 ? in[goff0] : 0.f;
    float dreg1 = (has1 && inb1) ? in[goff1] : 0.f;
    float4 un0 = up[0*16], un1 = up[1*16], un2 = up[2*16], un3 = up[3*16];

    float* smd = (float*)sm.ph.d;

    for (int ic0 = 0; ic0 < CIN; ic0 += 4) {
        smd[smoff0] = dreg0;
        if (has1) smd[smoff1] = dreg1;
        __syncthreads();   // d ready; also: everyone done reading prev V

        #pragma unroll
        for (int icb = 0; icb < 4; icb++) {
            const float* dd = sm.ph.d[icb];
            float R0 = dd[a00] + sa * dd[a10];
            float R1 = dd[a01] + sa * dd[a11];
            sm.ph.V[icb][k][slot] = R0 + sb * R1;
        }
        __syncthreads();   // V ready; d free

        int icn = (ic0 + 4 < CIN) ? ic0 + 4 : ic0;
        float4 u0 = un0, u1 = un1, u2 = un2, u3 = un3;
        un0 = up[(size_t)(icn+0)*16];
        un1 = up[(size_t)(icn+1)*16];
        un2 = up[(size_t)(icn+2)*16];
        un3 = up[(size_t)(icn+3)*16];
        dreg0 = inb0 ? in[(size_t)icn*HWX + goff0] : 0.f;
        if (has1) dreg1 = inb1 ? in[(size_t)icn*HWX + goff1] : 0.f;

        #pragma unroll
        for (int icb = 0; icb < 4; icb++) {
            float4 u = (icb == 0) ? u0 : (icb == 1) ? u1 : (icb == 2) ? u2 : u3;
            const float4* vr = (const float4*)sm.ph.V[icb][k];
            #pragma unroll
            for (int w = 0; w < 4; w++) {
                float4 vv = vr[w];
                float tv[4] = {vv.x, vv.y, vv.z, vv.w};
                #pragma unroll
                for (int q = 0; q < 4; q++) {
                    int t = w*4 + q;
                    acc[0][t] = fmaf(u.x, tv[q], acc[0][t]);
                    acc[1][t] = fmaf(u.y, tv[q], acc[1][t]);
                    acc[2][t] = fmaf(u.z, tv[q], acc[2][t]);
                    acc[3][t] = fmaf(u.w, tv[q], acc[3][t]);
                }
            }
        }
    }

    #pragma unroll
    for (int h = 0; h < 2; h++) {
        __syncthreads();
        if ((slot >> 3) == h) {
            int ocl = (slot & 7) * 4;
            #pragma unroll
            for (int j = 0; j < 4; j++)
                #pragma unroll
                for (int t = 0; t < 16; t++)
                    sm.M[k][ocl + j][t] = acc[j][t];
        }
        __syncthreads();
        #pragma unroll
        for (int q = tid; q < 512; q += 256) {
            int ocq = q >> 4, tile = q & 15;
            int oc = h*32 + ocq;
            float m[16];
            #pragma unroll
            for (int kk = 0; kk < 16; kk++) m[kk] = sm.M[kk][ocq][tile];
            float s0[4], s1[4];
            #pragma unroll
            for (int b = 0; b < 4; b++) {
                s0[b] = m[0*4+b] + m[1*4+b] + m[2*4+b];
                s1[b] = m[1*4+b] - m[2*4+b] - m[3*4+b];
            }
            float y00 = s0[0] + s0[1] + s0[2];
            float y01 = s0[1] - s0[2] - s0[3];
            float y10 = s1[0] + s1[1] + s1[2];
            float y11 = s1[1] - s1[2] - s1[3];
            float s = sc[oc], bb = bi[oc];
            int y = oy0 + (tile >> 2)*2;
            int x = ox0 + (tile & 3)*2;
            float* o0 = out + (size_t)oc*HWX + y*WW + x;
            o0[0]      = fmaxf(fmaf(y00, s, bb), 0.f);
            o0[1]      = fmaxf(fmaf(y01, s, bb), 0.f);
            o0[WW]     = fmaxf(fmaf(y10, s, bb), 0.f);
            o0[WW + 1] = fmaxf(fmaf(y11, s, bb), 0.f);
        }
    }
}

// ---------------- hm final conv (64->3) + bias + sigmoid + fused hist1 ----------------
__global__ __launch_bounds__(256)
void conv2_hm_k(const float* __restrict__ W2s, const float* __restrict__ b2s)
{
    const float* __restrict__ in = g_h;
    float* __restrict__ out = g_hm;
    __shared__ float s_in[8][10][34];
    __shared__ float s_w[8][27];
    __shared__ unsigned int s_hist[2048];
    const int tx = threadIdx.x, ty = threadIdx.y;
    const int tid = ty*32 + tx;
    const int x0 = blockIdx.x * 32;
    const int y0 = blockIdx.y * 8;
    float acc[3] = {0.f, 0.f, 0.f};

    for (int i = tid; i < 2048; i += 256) s_hist[i] = 0u;

    for (int ic0 = 0; ic0 < 64; ic0 += 8) {
        for (int i = tid; i < 8*340; i += 256) {
            int icb = i / 340, j = i % 340;
            int r = j / 34, c = j % 34;
            int gy = y0 - 1 + r, gx = x0 - 1 + c;
            float v = 0.f;
            if (gy >= 0 && gy < HH && gx >= 0 && gx < WW)
                v = in[(size_t)(ic0 + icb)*HWX + gy*WW + gx];
            s_in[icb][r][c] = v;
        }
        if (tid < 216) {
            int icb = tid / 27, q = tid % 27;
            int o = q / 9, kk = q % 9;
            s_w[icb][q] = W2s[(o*64 + ic0 + icb)*9 + kk]; // branch 0 base
        }
        __syncthreads();
        #pragma unroll
        for (int icb = 0; icb < 8; icb++) {
            float r9[9];
            #pragma unroll
            for (int ky = 0; ky < 3; ky++)
                #pragma unroll
                for (int kx = 0; kx < 3; kx++) r9[ky*3+kx] = s_in[icb][ty + ky][tx + kx];
            #pragma unroll
            for (int o = 0; o < 3; o++)
                #pragma unroll
                for (int kk = 0; kk < 9; kk++) acc[o] = fmaf(r9[kk], s_w[icb][o*9+kk], acc[o]);
        }
        __syncthreads();
    }
    int x = x0 + tx, y = y0 + ty;
    if (x < WW && y < HH) {
        #pragma unroll
        for (int o = 0; o < 3; o++) {
            float v = acc[o] + b2s[o];
            float s = 1.f / (1.f + expf(-v));
            out[(size_t)o*HWX + y*WW + x] = s;
            atomicAdd(&s_hist[__float_as_uint(s) >> 21], 1u);
        }
    }
    __syncthreads();
    for (int i = tid; i < 2048; i += 256)
        if (s_hist[i]) atomicAdd(&g_hist1[i], s_hist[i]);
}

// ---------------- top-k: 2-level radix-select on float bits + bitonic sort ----------------
__global__ void select1_k() {
    __shared__ unsigned int s[2048];
    int t = threadIdx.x; // 1024
    s[t] = g_hist1[t]; s[t+1024] = g_hist1[t+1024];
    __syncthreads();
    for (int off = 1; off < 2048; off <<= 1) {
        unsigned int v0 = (t + off < 2048) ? s[t + off] : 0u;
        unsigned int v1 = (t + 1024 + off < 2048) ? s[t + 1024 + off] : 0u;
        __syncthreads();
        s[t] += v0; s[t+1024] += v1;
        __syncthreads();
    }
    for (int p = t; p < 2048; p += 1024) {
        if (s[p] >= KTOP && (p == 2047 || s[p+1] < KTOP)) {
            g_T1 = (unsigned int)p;
            g_above1 = (p < 2047) ? s[p+1] : 0u;
        }
    }
}

__global__ void hist2_k() {
    __shared__ unsigned int h[2048];
    int t = threadIdx.x;
    unsigned int T1 = g_T1;
    for (int i = t; i < 2048; i += blockDim.x) h[i] = 0u;
    __syncthreads();
    for (int i = blockIdx.x * blockDim.x + t; i < NHM; i += gridDim.x * blockDim.x) {
        unsigned int bits = __float_as_uint(g_hm[i]);
        if ((bits >> 21) == T1) atomicAdd(&h[(bits >> 10) & 0x7FFu], 1u);
    }
    __syncthreads();
    for (int i = t; i < 2048; i += blockDim.x)
        if (h[i]) atomicAdd(&g_hist2[i], h[i]);
}

__global__ void select2_k() {
    __shared__ unsigned int s[2048];
    int t = threadIdx.x;
    unsigned int need = KTOP - g_above1;
    s[t] = g_hist2[t]; s[t+1024] = g_hist2[t+1024];
    __syncthreads();
    for (int off = 1; off < 2048; off <<= 1) {
        unsigned int v0 = (t + off < 2048) ? s[t + off] : 0u;
        unsigned int v1 = (t + 1024 + off < 2048) ? s[t + 1024 + off] : 0u;
        __syncthreads();
        s[t] += v0; s[t+1024] += v1;
        __syncthreads();
    }
    for (int p = t; p < 2048; p += 1024) {
        if (s[p] >= need && (p == 2047 || s[p+1] < need)) g_T2 = (unsigned int)p;
    }
}

__global__ void compact_k() {
    unsigned int T1 = g_T1, T2 = g_T2;
    for (int i = blockIdx.x * blockDim.x + threadIdx.x; i < NHM; i += gridDim.x * blockDim.x) {
        float v = g_hm[i];
        unsigned int bits = __float_as_uint(v);
        unsigned int b1 = bits >> 21;
        bool take = (b1 > T1) || (b1 == T1 && ((bits >> 10) & 0x7FFu) >= T2);
        if (take) {
            unsigned int pos = atomicAdd(&g_cand_count, 1u);
            if (pos < CANDS) { g_cand_val[pos] = v; g_cand_idx[pos] = i; }
        }
    }
}

// dynamic-size bitonic: sort next-pow2(M) elements only
__global__ void sort_topk_k() {
    __shared__ float sv[CANDS];
    __shared__ int   si[CANDS];
    int t = threadIdx.x; // 1024
    unsigned int M = g_cand_count; if (M > CANDS) M = CANDS;
    int Mp = 512; while (Mp < (int)M) Mp <<= 1;   // 512..4096 (M >= KTOP=500 guaranteed)
    for (int e = t; e < Mp; e += 1024) {
        if (e < (int)M) { sv[e] = g_cand_val[e]; si[e] = g_cand_idx[e]; }
        else            { sv[e] = -1.f;          si[e] = 0x7fffffff; }
    }
    __syncthreads();
    for (int k = 2; k <= Mp; k <<= 1) {
        for (int j = k >> 1; j > 0; j >>= 1) {
            for (int e = t; e < Mp; e += 1024) {
                int p = e ^ j;
                if (p > e) {
                    bool asc = ((e & k) == 0);
                    float va = sv[e], vb = sv[p];
                    int   ia = si[e], ib = si[p];
                    bool b_first = (vb > va) || (vb == va && ib < ia);
                    if (b_first == asc) { sv[e]=vb; sv[p]=va; si[e]=ib; si[p]=ia; }
                }
            }
            __syncthreads();
        }
    }
    if (t < KTOP) { g_topk_val[t] = sv[t]; g_topk_idx[t] = si[t]; }
}

// ---------------- sparse branch eval (branches 1..5 at 500 positions) ----------------
// Thread owns 3 outputs sharing oc = tid%64 (p = tid/64, +4, +8): weights cached
// in registers per icl and reused across all 3 outputs.
__global__ __launch_bounds__(256)
void sparse_branch_k(const float* __restrict__ W2s, const float* __restrict__ b2s) {
    __shared__ float sm_in[25*64];
    __shared__ float sm_w[8*576];
    __shared__ float sm_h[576];
    int det = blockIdx.x;
    int b = blockIdx.y + 1; // branches 1..5
    int tid = threadIdx.x;
    int idx = g_topk_idx[det];
    int sp = idx % HWX;
    int cy = sp / WW, cx = sp % WW;

    const int oc = tid & 63;
    const int p0 = tid >> 6;          // 0..3
    const bool has2 = (tid < 64);     // third output p = 8

    for (int i = tid; i < 1600; i += 256) {
        int p = i / 64, ic = i % 64;
        int gy = cy + p/5 - 2, gx = cx + p%5 - 2;
        float v = 0.f;
        if (gy >= 0 && gy < HH && gx >= 0 && gx < WW)
            v = g_shared[(size_t)ic*HWX + gy*WW + gx];
        sm_in[p*64 + ic] = v;
    }
    __syncthreads();

    float a[3] = {0.f, 0.f, 0.f};
    // per-output window bases (py*5+px for p, p+4, p+8)
    int pb[3];
    #pragma unroll
    for (int j = 0; j < 3; j++) {
        int p = p0 + j*4;
        pb[j] = (p/3)*5 + (p%3);
    }

    for (int c = 0; c < 8; c++) {
        int ic0 = c * 8;
        const float* wb = g_W1t + (size_t)(b*64 + ic0) * 576;
        for (int i = tid; i < 4608; i += 256) sm_w[i] = wb[i];
        __syncthreads();
        #pragma unroll
        for (int icl = 0; icl < 8; icl++) {
            const float* wrow = sm_w + icl*576 + oc*9;
            float w9[9];
            #pragma unroll
            for (int t2 = 0; t2 < 9; t2++) w9[t2] = wrow[t2];
            const float* inb = sm_in + ic0 + icl;
            #pragma unroll
            for (int j = 0; j < 3; j++) {
                if (j < 2 || has2) {
                    float s = a[j];
                    #pragma unroll
                    for (int ky = 0; ky < 3; ky++)
                        #pragma unroll
                        for (int kx = 0; kx < 3; kx++)
                            s = fmaf(inb[(pb[j] + ky*5 + kx)*64], w9[ky*3+kx], s);
                    a[j] = s;
                }
            }
        }
        __syncthreads();
    }

    // BN + ReLU + zero out-of-image conv1 pixels
    {
        #pragma unroll
        for (int q = 0; q < 3; q++) {
            int o = tid + q*256;
            if (o < 576) {
                int p = o / 64;
                float v = fmaf(a[q], g_sc1[b*64+oc], g_bi1[b*64+oc]);
                v = fmaxf(v, 0.f);
                int gy = cy + p/3 - 1, gx = cx + p%3 - 1;
                if (gy < 0 || gy >= HH || gx < 0 || gx >= WW) v = 0.f;
                sm_h[p*64 + oc] = v;
            }
        }
    }
    __syncthreads();

    int warp = tid >> 5, lane = tid & 31;
    if (warp < 3) {
        const float* w2 = W2s + (size_t)((b*3 + warp) * 64) * 9;
        float sum = 0.f;
        for (int t2 = lane; t2 < 576; t2 += 32) {
            int oc2 = t2 / 9, p = t2 % 9;
            sum = fmaf(sm_h[p*64 + oc2], w2[t2], sum);
        }
        #pragma unroll
        for (int off = 16; off > 0; off >>= 1)
            sum += __shfl_down_sync(0xFFFFFFFFu, sum, off);
        if (lane == 0)
            g_gather[((b-1)*KTOP + det)*3 + warp] = sum + b2s[b*3 + warp];
    }
}

// ---------------- decode ----------------
__global__ void decode_k(float* __restrict__ out) {
    int k = blockIdx.x * blockDim.x + threadIdx.x;
    if (k >= KTOP) return;
    float s = g_topk_val[k];
    int idx = g_topk_idx[k];
    int cls = idx / HWX;
    int sp  = idx % HWX;
    float ys = (float)(sp / WW);
    float xs = (float)(sp % WW);
    const float* gC = &g_gather[(0*KTOP + k)*3];
    const float* gZ = &g_gather[(1*KTOP + k)*3];
    const float* gD = &g_gather[(2*KTOP + k)*3];
    const float* gR = &g_gather[(3*KTOP + k)*3];
    const float* gI = &g_gather[(4*KTOP + k)*3];
    float xg = (xs + gC[0]) * 0.4f - 75.2f;
    float yg = (ys + gC[1]) * 0.4f - 75.2f;
    float cz = gZ[0];
    float d0 = expf(gD[0]), d1 = expf(gD[1]), d2 = expf(gD[2]);
    float heading = atan2f(gR[1], gR[0]);
    float iou = (gI[0] + 1.f) * 0.5f;
    iou = fminf(fmaxf(iou, 0.f), 1.f);
    const float rect[3] = {0.68f, 0.71f, 0.65f};
    float r = rect[cls];
    float sc = powf(s, 1.f - r) * powf(iou, r);
    if (!(sc > 0.1f)) sc = 0.f;
    out[k*7 + 0] = xg;
    out[k*7 + 1] = yg;
    out[k*7 + 2] = cz;
    out[k*7 + 3] = d0;
    out[k*7 + 4] = d1;
    out[k*7 + 5] = d2;
    out[k*7 + 6] = heading;
    out[KTOP*7 + k] = sc;            // scores at 3500..3999
    out[KTOP*7 + KTOP + k] = (float)cls; // cls at 4000..4499
}

// ---------------- launch ----------------
extern "C" void kernel_launch(void* const* d_in, const int* in_sizes, int n_in,
                              void* d_out, int out_size) {
    const float* x     = (const float*)d_in[0];
    const float* W_sh  = (const float*)d_in[1];
    const float* bn_sh = (const float*)d_in[2];
    const float* W1s   = (const float*)d_in[3];
    const float* bn1s  = (const float*)d_in[4];
    const float* W2s   = (const float*)d_in[5];
    const float* b2s   = (const float*)d_in[6];
    float* out = (float*)d_out;

    setup_k<<<(out_size + 255)/256 > 8 ? (out_size + 255)/256 : 8, 256>>>(bn_sh, bn1s, out, out_size);
    wg_transform_all_k<<<(64*256 + 64*64 + 255)/256, 256>>>(W_sh, W1s);

    dim3 wgrid(47, 47);
    winograd_k<256, 0><<<wgrid, 256>>>(x);        // shared conv 256->64
    winograd_k<64, 1><<<wgrid, 256>>>(nullptr);   // hm conv1 64->64

    transpose_w1_k<<<(6*64*64*9 + 511)/512, 512>>>(W1s);

    dim3 cgrid(12, 47), cblk(32, 8);
    conv2_hm_k<<<cgrid, cblk>>>(W2s, b2s);

    select1_k<<<1, 1024>>>();
    hist2_k<<<512, 512>>>();
    select2_k<<<1, 1024>>>();
    compact_k<<<512, 512>>>();
    sort_topk_k<<<1, 1024>>>();

    dim3 sgrid(KTOP, 5);
    sparse_branch_k<<<sgrid, 256>>>(W2s, b2s);
    decode_k<<<2, 256>>>(out);
}

// round 15
// speedup vs baseline: 1.1877x; 1.0182x over previous
#include <cuda_runtime.h>

#define HH 376
#define WW 376
#define HWX (HH*WW)          // 141376
#define NHM (3*HWX)          // 424128
#define KTOP 500
#define CANDS 4096

// ---------------- scratch (device globals: no allocation allowed) ----------------
__device__ float g_shared[64 * HWX];     // shared conv output (BN+ReLU)
__device__ float g_h[64 * HWX];          // hm branch conv1 output
__device__ float g_hm[3 * HWX];          // sigmoid heatmap
__device__ float g_Ush[16 * 256 * 64];   // winograd weights shared conv: [k16][ic][oc]
__device__ float g_U1[16 * 64 * 64];     // winograd weights hm conv1 (branch 0)
__device__ float g_W1t[6 * 64 * 64 * 9]; // [b][ic][oc][9] (for sparse path)
__device__ float g_sc_sh[64], g_bi_sh[64];
__device__ float g_sc1[6 * 64], g_bi1[6 * 64];
__device__ unsigned int g_hist1[2048], g_hist2[2048];
__device__ unsigned int g_T1, g_above1, g_T2;
__device__ unsigned int g_cand_count;
__device__ float g_cand_val[CANDS];
__device__ int   g_cand_idx[CANDS];
__device__ float g_topk_val[512];
__device__ int   g_topk_idx[512];
__device__ float g_gather[5 * KTOP * 3]; // [branch-1][det][3]

// ---------------- merged setup: zero hists/out + BN prep ----------------
__global__ void setup_k(const float* __restrict__ bn_sh, const float* __restrict__ bn1s,
                        float* __restrict__ out, int out_n) {
    int i = blockIdx.x * blockDim.x + threadIdx.x;
    if (i < 2048) { g_hist1[i] = 0u; g_hist2[i] = 0u; }
    if (i == 0) g_cand_count = 0u;
    if (i < out_n) out[i] = 0.f;
    if (i < 64) {
        int c = i;
        float g = bn_sh[0*64+c], b = bn_sh[1*64+c], m = bn_sh[2*64+c], v = bn_sh[3*64+c];
        float sc = g * rsqrtf(v + 1e-5f);
        g_sc_sh[c] = sc; g_bi_sh[c] = b - m * sc;
        for (int br = 0; br < 6; br++) {
            const float* p = bn1s + br * 4 * 64;
            float g1 = p[0*64+c], b1 = p[1*64+c], m1 = p[2*64+c], v1 = p[3*64+c];
            float s1 = g1 * rsqrtf(v1 + 1e-5f);
            g_sc1[br*64+c] = s1; g_bi1[br*64+c] = b1 - m1 * s1;
        }
    }
}

// ---------------- Winograd weight transform: U = G g G^T ----------------
// G = [[1,0,0],[.5,.5,.5],[.5,-.5,.5],[0,0,1]]
__device__ __forceinline__ void wg_fill(const float* __restrict__ g9, float u[4][4]) {
    float t[4][3];
    #pragma unroll
    for (int c = 0; c < 3; c++) {
        float g0 = g9[0*3+c], g1 = g9[1*3+c], g2 = g9[2*3+c];
        t[0][c] = g0;
        t[1][c] = 0.5f*(g0 + g1 + g2);
        t[2][c] = 0.5f*(g0 - g1 + g2);
        t[3][c] = g2;
    }
    #pragma unroll
    for (int r = 0; r < 4; r++) {
        float a = t[r][0], b = t[r][1], c = t[r][2];
        u[r][0] = a;
        u[r][1] = 0.5f*(a + b + c);
        u[r][2] = 0.5f*(a - b + c);
        u[r][3] = c;
    }
}

// merged: W_sh [oc64][ic256][9] -> g_Ush ; W1s branch0 -> g_U1
__global__ void wg_transform_all_k(const float* __restrict__ wsh, const float* __restrict__ w1) {
    int i = blockIdx.x * blockDim.x + threadIdx.x;
    if (i < 64*256) {
        int ic = i % 256, oc = i / 256;
        float u[4][4];
        wg_fill(wsh + (size_t)i*9, u);
        #pragma unroll
        for (int r = 0; r < 4; r++)
            #pragma unroll
            for (int c = 0; c < 4; c++)
                g_Ush[(r*4+c)*(256*64) + ic*64 + oc] = u[r][c];
    } else if (i < 64*256 + 64*64) {
        int j = i - 64*256;
        int ic = j % 64, oc = j / 64;
        float u[4][4];
        wg_fill(w1 + (size_t)j*9, u);
        #pragma unroll
        for (int r = 0; r < 4; r++)
            #pragma unroll
            for (int c = 0; c < 4; c++)
                g_U1[(r*4+c)*(64*64) + ic*64 + oc] = u[r][c];
    }
}

// W1s [b][oc64][ic64][9] -> g_W1t [b][ic][oc][9]  (sparse path)
__global__ void transpose_w1_k(const float* __restrict__ w) {
    int i = blockIdx.x * blockDim.x + threadIdx.x;
    if (i >= 6*64*64*9) return;
    int k = i % 9; int r = i / 9; int ic = r % 64; r /= 64; int oc = r % 64; int b = r / 64;
    g_W1t[(((b*64 + ic)*64) + oc)*9 + k] = w[i];
}

// ---------------- Winograd F(2x2,3x3) conv + BN + ReLU (Cout=64) ----------------
// R11-proven config: 2 CTAs/SM, 64 oc/block, register-resident float4 U double-buffer.
template<int CIN, int MODE>
__global__ __launch_bounds__(256, 2)
void winograd_k(const float* __restrict__ xin)
{
    const float* __restrict__ in = (MODE == 0) ? xin : g_shared;
    const float* __restrict__ Ug = (MODE == 0) ? g_Ush : g_U1;
    const float* __restrict__ sc = (MODE == 0) ? g_sc_sh : g_sc1;
    const float* __restrict__ bi = (MODE == 0) ? g_bi_sh : g_bi1;
    float* __restrict__ out      = (MODE == 0) ? g_shared : g_h;

    __shared__ union {
        struct {
            float V[4][16][16];   // [icb][k][tile] rows contiguous (LDS.128 in core)
            float d[4][112];      // [icb][r*11+c], 110 used
        } ph;
        float M[16][32][16];      // epilogue exchange: [k][oc-half][tile]
    } sm;

    const int tid = threadIdx.x;
    const int ox0 = blockIdx.x * 8, oy0 = blockIdx.y * 8;
    const int k = tid >> 4;      // transform point 0..15 (V + core)
    const int slot = tid & 15;   // V-phase tile / core oc-group

    int goff0 = 0, goff1 = 0, smoff0 = 0, smoff1 = 0;
    bool inb0 = false, inb1 = false;
    {
        int p = tid % 100, icb = tid / 100;
        int lr = p / 10, lc = p % 10;
        int gy = oy0 - 1 + lr, gx = ox0 - 1 + lc;
        inb0 = (gy >= 0 && gy < HH && gx >= 0 && gx < WW);
        goff0 = icb*HWX + gy*WW + gx;
        smoff0 = icb*112 + lr*11 + lc;
    }
    const bool has1 = (tid < 144);
    if (has1) {
        int i = tid + 256;
        int p = i % 100, icb = i / 100;
        int lr = p / 10, lc = p % 10;
        int gy = oy0 - 1 + lr, gx = ox0 - 1 + lc;
        inb1 = (gy >= 0 && gy < HH && gx >= 0 && gx < WW);
        goff1 = icb*HWX + gy*WW + gx;
        smoff1 = icb*112 + lr*11 + lc;
    }

    const int va = k >> 2, vb = k & 3;
    const int ia0 = (va == 0) ? 0 : ((va == 2) ? 2 : 1);
    const int ia1 = (va < 2) ? 2 : ((va == 2) ? 1 : 3);
    const float sa = (va == 1) ? 1.f : -1.f;
    const int ib0 = (vb == 0) ? 0 : ((vb == 2) ? 2 : 1);
    const int ib1 = (vb < 2) ? 2 : ((vb == 2) ? 1 : 3);
    const float sb = (vb == 1) ? 1.f : -1.f;
    const int r0 = (slot >> 2)*2 + ia0, r1 = (slot >> 2)*2 + ia1;
    const int c0 = (slot & 3)*2 + ib0,  c1 = (slot & 3)*2 + ib1;
    const int a00 = r0*11 + c0, a01 = r0*11 + c1;
    const int a10 = r1*11 + c0, a11 = r1*11 + c1;

    const float4* up = (const float4*)Ug + (size_t)k*(CIN*16) + slot;

    float acc[4][16];
    #pragma unroll
    for (int j = 0; j < 4; j++)
        #pragma unroll
        for (int t = 0; t < 16; t++) acc[j][t] = 0.f;

    float dreg0 = inb0 ? in[goff0] : 0.f;
    float dreg1 = (has1 && inb1) ? in[goff1] : 0.f;
    float4 un0 = up[0*16], un1 = up[1*16], un2 = up[2*16], un3 = up[3*16];

    float* smd = (float*)sm.ph.d;

    for (int ic0 = 0; ic0 < CIN; ic0 += 4) {
        smd[smoff0] = dreg0;
        if (has1) smd[smoff1] = dreg1;
        __syncthreads();   // d ready; also: everyone done reading prev V

        #pragma unroll
        for (int icb = 0; icb < 4; icb++) {
            const float* dd = sm.ph.d[icb];
            float R0 = dd[a00] + sa * dd[a10];
            float R1 = dd[a01] + sa * dd[a11];
            sm.ph.V[icb][k][slot] = R0 + sb * R1;
        }
        __syncthreads();   // V ready; d free

        int icn = (ic0 + 4 < CIN) ? ic0 + 4 : ic0;
        float4 u0 = un0, u1 = un1, u2 = un2, u3 = un3;
        un0 = up[(size_t)(icn+0)*16];
        un1 = up[(size_t)(icn+1)*16];
        un2 = up[(size_t)(icn+2)*16];
        un3 = up[(size_t)(icn+3)*16];
        dreg0 = inb0 ? in[(size_t)icn*HWX + goff0] : 0.f;
        if (has1) dreg1 = inb1 ? in[(size_t)icn*HWX + goff1] : 0.f;

        #pragma unroll
        for (int icb = 0; icb < 4; icb++) {
            float4 u = (icb == 0) ? u0 : (icb == 1) ? u1 : (icb == 2) ? u2 : u3;
            const float4* vr = (const float4*)sm.ph.V[icb][k];
            #pragma unroll
            for (int w = 0; w < 4; w++) {
                float4 vv = vr[w];
                float tv[4] = {vv.x, vv.y, vv.z, vv.w};
                #pragma unroll
                for (int q = 0; q < 4; q++) {
                    int t = w*4 + q;
                    acc[0][t] = fmaf(u.x, tv[q], acc[0][t]);
                    acc[1][t] = fmaf(u.y, tv[q], acc[1][t]);
                    acc[2][t] = fmaf(u.z, tv[q], acc[2][t]);
                    acc[3][t] = fmaf(u.w, tv[q], acc[3][t]);
                }
            }
        }
    }

    #pragma unroll
    for (int h = 0; h < 2; h++) {
        __syncthreads();
        if ((slot >> 3) == h) {
            int ocl = (slot & 7) * 4;
            #pragma unroll
            for (int j = 0; j < 4; j++)
                #pragma unroll
                for (int t = 0; t < 16; t++)
                    sm.M[k][ocl + j][t] = acc[j][t];
        }
        __syncthreads();
        #pragma unroll
        for (int q = tid; q < 512; q += 256) {
            int ocq = q >> 4, tile = q & 15;
            int oc = h*32 + ocq;
            float m[16];
            #pragma unroll
            for (int kk = 0; kk < 16; kk++) m[kk] = sm.M[kk][ocq][tile];
            float s0[4], s1[4];
            #pragma unroll
            for (int b = 0; b < 4; b++) {
                s0[b] = m[0*4+b] + m[1*4+b] + m[2*4+b];
                s1[b] = m[1*4+b] - m[2*4+b] - m[3*4+b];
            }
            float y00 = s0[0] + s0[1] + s0[2];
            float y01 = s0[1] - s0[2] - s0[3];
            float y10 = s1[0] + s1[1] + s1[2];
            float y11 = s1[1] - s1[2] - s1[3];
            float s = sc[oc], bb = bi[oc];
            int y = oy0 + (tile >> 2)*2;
            int x = ox0 + (tile & 3)*2;
            float* o0 = out + (size_t)oc*HWX + y*WW + x;
            o0[0]      = fmaxf(fmaf(y00, s, bb), 0.f);
            o0[1]      = fmaxf(fmaf(y01, s, bb), 0.f);
            o0[WW]     = fmaxf(fmaf(y10, s, bb), 0.f);
            o0[WW + 1] = fmaxf(fmaf(y11, s, bb), 0.f);
        }
    }
}

// ---------------- hm final conv (64->3) + bias + sigmoid + fused hist1 ----------------
__global__ __launch_bounds__(256)
void conv2_hm_k(const float* __restrict__ W2s, const float* __restrict__ b2s)
{
    const float* __restrict__ in = g_h;
    float* __restrict__ out = g_hm;
    __shared__ float s_in[8][10][34];
    __shared__ float s_w[8][27];
    __shared__ unsigned int s_hist[2048];
    const int tx = threadIdx.x, ty = threadIdx.y;
    const int tid = ty*32 + tx;
    const int x0 = blockIdx.x * 32;
    const int y0 = blockIdx.y * 8;
    float acc[3] = {0.f, 0.f, 0.f};

    for (int i = tid; i < 2048; i += 256) s_hist[i] = 0u;

    for (int ic0 = 0; ic0 < 64; ic0 += 8) {
        for (int i = tid; i < 8*340; i += 256) {
            int icb = i / 340, j = i % 340;
            int r = j / 34, c = j % 34;
            int gy = y0 - 1 + r, gx = x0 - 1 + c;
            float v = 0.f;
            if (gy >= 0 && gy < HH && gx >= 0 && gx < WW)
                v = in[(size_t)(ic0 + icb)*HWX + gy*WW + gx];
            s_in[icb][r][c] = v;
        }
        if (tid < 216) {
            int icb = tid / 27, q = tid % 27;
            int o = q / 9, kk = q % 9;
            s_w[icb][q] = W2s[(o*64 + ic0 + icb)*9 + kk]; // branch 0 base
        }
        __syncthreads();
        #pragma unroll
        for (int icb = 0; icb < 8; icb++) {
            float r9[9];
            #pragma unroll
            for (int ky = 0; ky < 3; ky++)
                #pragma unroll
                for (int kx = 0; kx < 3; kx++) r9[ky*3+kx] = s_in[icb][ty + ky][tx + kx];
            #pragma unroll
            for (int o = 0; o < 3; o++)
                #pragma unroll
                for (int kk = 0; kk < 9; kk++) acc[o] = fmaf(r9[kk], s_w[icb][o*9+kk], acc[o]);
        }
        __syncthreads();
    }
    int x = x0 + tx, y = y0 + ty;
    if (x < WW && y < HH) {
        #pragma unroll
        for (int o = 0; o < 3; o++) {
            float v = acc[o] + b2s[o];
            float s = 1.f / (1.f + expf(-v));
            out[(size_t)o*HWX + y*WW + x] = s;
            atomicAdd(&s_hist[__float_as_uint(s) >> 21], 1u);
        }
    }
    __syncthreads();
    for (int i = tid; i < 2048; i += 256)
        if (s_hist[i]) atomicAdd(&g_hist1[i], s_hist[i]);
}

// ---------------- top-k: 2-level radix-select on float bits + bitonic sort ----------------
__global__ void select1_k() {
    __shared__ unsigned int s[2048];
    int t = threadIdx.x; // 1024
    s[t] = g_hist1[t]; s[t+1024] = g_hist1[t+1024];
    __syncthreads();
    for (int off = 1; off < 2048; off <<= 1) {
        unsigned int v0 = (t + off < 2048) ? s[t + off] : 0u;
        unsigned int v1 = (t + 1024 + off < 2048) ? s[t + 1024 + off] : 0u;
        __syncthreads();
        s[t] += v0; s[t+1024] += v1;
        __syncthreads();
    }
    for (int p = t; p < 2048; p += 1024) {
        if (s[p] >= KTOP && (p == 2047 || s[p+1] < KTOP)) {
            g_T1 = (unsigned int)p;
            g_above1 = (p < 2047) ? s[p+1] : 0u;
        }
    }
}

// float4-vectorized: NHM = 424128 = 4 * 106032
__global__ void hist2_k() {
    __shared__ unsigned int h[2048];
    int t = threadIdx.x;
    unsigned int T1 = g_T1;
    for (int i = t; i < 2048; i += blockDim.x) h[i] = 0u;
    __syncthreads();
    const float4* hm4 = (const float4*)g_hm;
    for (int i = blockIdx.x * blockDim.x + t; i < NHM/4; i += gridDim.x * blockDim.x) {
        float4 v = hm4[i];
        unsigned int b0 = __float_as_uint(v.x), b1 = __float_as_uint(v.y);
        unsigned int b2 = __float_as_uint(v.z), b3 = __float_as_uint(v.w);
        if ((b0 >> 21) == T1) atomicAdd(&h[(b0 >> 10) & 0x7FFu], 1u);
        if ((b1 >> 21) == T1) atomicAdd(&h[(b1 >> 10) & 0x7FFu], 1u);
        if ((b2 >> 21) == T1) atomicAdd(&h[(b2 >> 10) & 0x7FFu], 1u);
        if ((b3 >> 21) == T1) atomicAdd(&h[(b3 >> 10) & 0x7FFu], 1u);
    }
    __syncthreads();
    for (int i = t; i < 2048; i += blockDim.x)
        if (h[i]) atomicAdd(&g_hist2[i], h[i]);
}

__global__ void select2_k() {
    __shared__ unsigned int s[2048];
    int t = threadIdx.x;
    unsigned int need = KTOP - g_above1;
    s[t] = g_hist2[t]; s[t+1024] = g_hist2[t+1024];
    __syncthreads();
    for (int off = 1; off < 2048; off <<= 1) {
        unsigned int v0 = (t + off < 2048) ? s[t + off] : 0u;
        unsigned int v1 = (t + 1024 + off < 2048) ? s[t + 1024 + off] : 0u;
        __syncthreads();
        s[t] += v0; s[t+1024] += v1;
        __syncthreads();
    }
    for (int p = t; p < 2048; p += 1024) {
        if (s[p] >= need && (p == 2047 || s[p+1] < need)) g_T2 = (unsigned int)p;
    }
}

// float4-vectorized compaction
__global__ void compact_k() {
    unsigned int T1 = g_T1, T2 = g_T2;
    const float4* hm4 = (const float4*)g_hm;
    for (int i = blockIdx.x * blockDim.x + threadIdx.x; i < NHM/4; i += gridDim.x * blockDim.x) {
        float4 v4 = hm4[i];
        float vs[4] = {v4.x, v4.y, v4.z, v4.w};
        #pragma unroll
        for (int j = 0; j < 4; j++) {
            unsigned int bits = __float_as_uint(vs[j]);
            unsigned int b1 = bits >> 21;
            bool take = (b1 > T1) || (b1 == T1 && ((bits >> 10) & 0x7FFu) >= T2);
            if (take) {
                unsigned int pos = atomicAdd(&g_cand_count, 1u);
                if (pos < CANDS) { g_cand_val[pos] = vs[j]; g_cand_idx[pos] = i*4 + j; }
            }
        }
    }
}

// dynamic-size bitonic: sort next-pow2(M) elements only
__global__ void sort_topk_k() {
    __shared__ float sv[CANDS];
    __shared__ int   si[CANDS];
    int t = threadIdx.x; // 1024
    unsigned int M = g_cand_count; if (M > CANDS) M = CANDS;
    int Mp = 512; while (Mp < (int)M) Mp <<= 1;   // 512..4096 (M >= KTOP=500 guaranteed)
    for (int e = t; e < Mp; e += 1024) {
        if (e < (int)M) { sv[e] = g_cand_val[e]; si[e] = g_cand_idx[e]; }
        else            { sv[e] = -1.f;          si[e] = 0x7fffffff; }
    }
    __syncthreads();
    for (int k = 2; k <= Mp; k <<= 1) {
        for (int j = k >> 1; j > 0; j >>= 1) {
            for (int e = t; e < Mp; e += 1024) {
                int p = e ^ j;
                if (p > e) {
                    bool asc = ((e & k) == 0);
                    float va = sv[e], vb = sv[p];
                    int   ia = si[e], ib = si[p];
                    bool b_first = (vb > va) || (vb == va && ib < ia);
                    if (b_first == asc) { sv[e]=vb; sv[p]=va; si[e]=ib; si[p]=ia; }
                }
            }
            __syncthreads();
        }
    }
    if (t < KTOP) { g_topk_val[t] = sv[t]; g_topk_idx[t] = si[t]; }
}

// ---------------- sparse branch eval (branches 1..5 at 500 positions) ----------------
__device__ __forceinline__ float acc_out(const float* sm_in, const float* sm_w, int o, int ic0) {
    int p = o / 64, oc = o % 64, py = p / 3, px = p % 3;
    float part = 0.f;
    #pragma unroll
    for (int icl = 0; icl < 8; icl++) {
        const float* wrow = sm_w + icl*576 + oc*9;
        #pragma unroll
        for (int ky = 0; ky < 3; ky++)
            #pragma unroll
            for (int kx = 0; kx < 3; kx++) {
                int pin = (py + ky)*5 + (px + kx);
                part = fmaf(sm_in[pin*64 + ic0 + icl], wrow[ky*3+kx], part);
            }
    }
    return part;
}

__global__ __launch_bounds__(256)
void sparse_branch_k(const float* __restrict__ W2s, const float* __restrict__ b2s) {
    __shared__ float sm_in[25*64];
    __shared__ float sm_w[8*576];
    __shared__ float sm_h[576];
    int det = blockIdx.x;
    int b = blockIdx.y + 1; // branches 1..5
    int tid = threadIdx.x;
    int idx = g_topk_idx[det];
    int sp = idx % HWX;
    int cy = sp / WW, cx = sp % WW;

    for (int i = tid; i < 1600; i += 256) {
        int p = i / 64, ic = i % 64;
        int gy = cy + p/5 - 2, gx = cx + p%5 - 2;
        float v = 0.f;
        if (gy >= 0 && gy < HH && gx >= 0 && gx < WW)
            v = g_shared[(size_t)ic*HWX + gy*WW + gx];
        sm_in[p*64 + ic] = v;
    }
    __syncthreads();

    float a0 = 0.f, a1 = 0.f, a2 = 0.f;
    for (int c = 0; c < 8; c++) {
        int ic0 = c * 8;
        const float* wb = g_W1t + (size_t)(b*64 + ic0) * 576;
        for (int i = tid; i < 4608; i += 256) sm_w[i] = wb[i];
        __syncthreads();
        a0 += acc_out(sm_in, sm_w, tid,       ic0);
        a1 += acc_out(sm_in, sm_w, tid + 256, ic0);
        if (tid < 64) a2 += acc_out(sm_in, sm_w, tid + 512, ic0);
        __syncthreads();
    }

    // BN + ReLU + zero out-of-image conv1 pixels
    {
        float accs[3] = {a0, a1, a2};
        int os[3] = {tid, tid + 256, tid + 512};
        #pragma unroll
        for (int q = 0; q < 3; q++) {
            int o = os[q];
            if (o < 576) {
                int p = o / 64, oc = o % 64;
                float v = fmaf(accs[q], g_sc1[b*64+oc], g_bi1[b*64+oc]);
                v = fmaxf(v, 0.f);
                int gy = cy + p/3 - 1, gx = cx + p%3 - 1;
                if (gy < 0 || gy >= HH || gx < 0 || gx >= WW) v = 0.f;
                sm_h[p*64 + oc] = v;
            }
        }
    }
    __syncthreads();

    int warp = tid >> 5, lane = tid & 31;
    if (warp < 3) {
        const float* w2 = W2s + (size_t)((b*3 + warp) * 64) * 9;
        float sum = 0.f;
        for (int t2 = lane; t2 < 576; t2 += 32) {
            int oc = t2 / 9, p = t2 % 9;
            sum = fmaf(sm_h[p*64 + oc], w2[t2], sum);
        }
        #pragma unroll
        for (int off = 16; off > 0; off >>= 1)
            sum += __shfl_down_sync(0xFFFFFFFFu, sum, off);
        if (lane == 0)
            g_gather[((b-1)*KTOP + det)*3 + warp] = sum + b2s[b*3 + warp];
    }
}

// ---------------- decode ----------------
__global__ void decode_k(float* __restrict__ out) {
    int k = blockIdx.x * blockDim.x + threadIdx.x;
    if (k >= KTOP) return;
    float s = g_topk_val[k];
    int idx = g_topk_idx[k];
    int cls = idx / HWX;
    int sp  = idx % HWX;
    float ys = (float)(sp / WW);
    float xs = (float)(sp % WW);
    const float* gC = &g_gather[(0*KTOP + k)*3];
    const float* gZ = &g_gather[(1*KTOP + k)*3];
    const float* gD = &g_gather[(2*KTOP + k)*3];
    const float* gR = &g_gather[(3*KTOP + k)*3];
    const float* gI = &g_gather[(4*KTOP + k)*3];
    float xg = (xs + gC[0]) * 0.4f - 75.2f;
    float yg = (ys + gC[1]) * 0.4f - 75.2f;
    float cz = gZ[0];
    float d0 = expf(gD[0]), d1 = expf(gD[1]), d2 = expf(gD[2]);
    float heading = atan2f(gR[1], gR[0]);
    float iou = (gI[0] + 1.f) * 0.5f;
    iou = fminf(fmaxf(iou, 0.f), 1.f);
    const float rect[3] = {0.68f, 0.71f, 0.65f};
    float r = rect[cls];
    float sc = powf(s, 1.f - r) * powf(iou, r);
    if (!(sc > 0.1f)) sc = 0.f;
    out[k*7 + 0] = xg;
    out[k*7 + 1] = yg;
    out[k*7 + 2] = cz;
    out[k*7 + 3] = d0;
    out[k*7 + 4] = d1;
    out[k*7 + 5] = d2;
    out[k*7 + 6] = heading;
    out[KTOP*7 + k] = sc;            // scores at 3500..3999
    out[KTOP*7 + KTOP + k] = (float)cls; // cls at 4000..4499
}

// ---------------- launch ----------------
extern "C" void kernel_launch(void* const* d_in, const int* in_sizes, int n_in,
                              void* d_out, int out_size) {
    const float* x     = (const float*)d_in[0];
    const float* W_sh  = (const float*)d_in[1];
    const float* bn_sh = (const float*)d_in[2];
    const float* W1s   = (const float*)d_in[3];
    const float* bn1s  = (const float*)d_in[4];
    const float* W2s   = (const float*)d_in[5];
    const float* b2s   = (const float*)d_in[6];
    float* out = (float*)d_out;

    setup_k<<<(out_size + 255)/256 > 8 ? (out_size + 255)/256 : 8, 256>>>(bn_sh, bn1s, out, out_size);
    wg_transform_all_k<<<(64*256 + 64*64 + 255)/256, 256>>>(W_sh, W1s);

    dim3 wgrid(47, 47);
    winograd_k<256, 0><<<wgrid, 256>>>(x);        // shared conv 256->64
    winograd_k<64, 1><<<wgrid, 256>>>(nullptr);   // hm conv1 64->64

    transpose_w1_k<<<(6*64*64*9 + 511)/512, 512>>>(W1s);

    dim3 cgrid(12, 47), cblk(32, 8);
    conv2_hm_k<<<cgrid, cblk>>>(W2s, b2s);

    select1_k<<<1, 1024>>>();
    hist2_k<<<512, 512>>>();
    select2_k<<<1, 1024>>>();
    compact_k<<<256, 512>>>();
    sort_topk_k<<<1, 1024>>>();

    dim3 sgrid(KTOP, 5);
    sparse_branch_k<<<sgrid, 256>>>(W2s, b2s);
    decode_k<<<2, 256>>>(out);
}